// round 3
// baseline (speedup 1.0000x reference)
#include <cuda_runtime.h>

#define NN 50000
#define EE 400000
#define DD 300
#define LL 5
#define CC 128
#define NGR 256
#define BN_EPS 1e-5f

// ---------------- static device scratch (no allocations allowed) ----------------
__device__ int   g_is64;           // 1 if index tensors are int64, 0 if int32
__device__ int   g_cnt[NN];
__device__ int   g_off[NN + 1];
__device__ int   g_pos[NN];
__device__ int   g_srcl[EE];
__device__ int   g_goff[NGR + 1];
__device__ __align__(16) float g_z0[(size_t)NN * DD];   // agg output / gemm2 output
__device__ __align__(16) float g_z1[(size_t)NN * DD];   // gemm1 output
__device__ __align__(16) float g_hbuf[(size_t)NN * DD]; // post-BN/ReLU hidden
__device__ float g_colsum[DD];
__device__ float g_colsq[DD];
__device__ float g_mu1[DD], g_rs1[DD], g_mu2[DD], g_rs2[DD];
__device__ __align__(16) float g_pooled[(size_t)(LL + 1) * NGR * DD];

__device__ __forceinline__ int idx_at(const void* p, long long i) {
    if (g_is64) return (int)((const long long*)p)[i];
    return ((const int*)p)[i];
}

// Detect int64 vs int32: for int64 values < 2^32, every odd 32-bit word is 0.
__global__ void k_detect(const void* ei) {
    const int* w = (const int*)ei;
    int all0 = 1;
    for (int i = 0; i < 128; i++)
        if (w[2 * i + 1] != 0) { all0 = 0; break; }
    g_is64 = all0;
}

// ---------------- setup kernels ----------------
__global__ void k_zero() {
    int i = blockIdx.x * blockDim.x + threadIdx.x;
    if (i < NN) g_cnt[i] = 0;
    if (i < DD) { g_colsum[i] = 0.f; g_colsq[i] = 0.f; }
}

__global__ void k_count(const void* __restrict__ ei) {
    int e = blockIdx.x * blockDim.x + threadIdx.x;
    if (e < EE) {
        int d = idx_at(ei, (long long)EE + e);
        d = max(0, min(NN - 1, d));
        atomicAdd(&g_cnt[d], 1);
    }
}

__global__ void k_scan() {
    __shared__ int s[1024];
    int t = threadIdx.x;
    int carry = 0;
    for (int base = 0; base < NN; base += 1024) {
        int v = (base + t < NN) ? g_cnt[base + t] : 0;
        s[t] = v;
        __syncthreads();
        for (int d = 1; d < 1024; d <<= 1) {
            int y = (t >= d) ? s[t - d] : 0;
            __syncthreads();
            s[t] += y;
            __syncthreads();
        }
        int incl = s[t];
        if (base + t < NN) {
            int ex = carry + incl - v;
            g_off[base + t] = ex;
            g_pos[base + t] = ex;
        }
        carry += s[1023];
        __syncthreads();
    }
    if (t == 0) g_off[NN] = carry;
}

__global__ void k_fill(const void* __restrict__ ei) {
    int e = blockIdx.x * blockDim.x + threadIdx.x;
    if (e < EE) {
        int d = idx_at(ei, (long long)EE + e);
        d = max(0, min(NN - 1, d));
        int srcv = idx_at(ei, e);
        srcv = max(0, min(NN - 1, srcv));
        int p = atomicAdd(&g_pos[d], 1);
        if (p >= 0 && p < EE) g_srcl[p] = srcv;
    }
}

__global__ void k_goff(const void* __restrict__ batch) {
    int g = blockIdx.x * blockDim.x + threadIdx.x;
    if (g > NGR) return;
    int lo = 0, hi = NN;
    while (lo < hi) {
        int mid = (lo + hi) >> 1;
        if (idx_at(batch, mid) < g) lo = mid + 1; else hi = mid;
    }
    g_goff[g] = lo;
}

// ---------------- aggregation: g_z0 = h + sum_{(s,i) in E} h[s] ----------------
__global__ void k_agg(const float* __restrict__ x, int useX) {
    const float* __restrict__ h = useX ? x : g_hbuf;
    int i = blockIdx.x;
    int t = threadIdx.x;                 // 128 threads
    size_t base = (size_t)i * DD;
    int s0 = g_off[i], s1 = g_off[i + 1];
    s0 = max(0, min(EE, s0));
    s1 = max(s0, min(EE, s1));
    bool v2 = (t < DD - 256);            // t < 44
    float a0 = h[base + t];
    float a1 = h[base + t + 128];
    float a2 = v2 ? h[base + t + 256] : 0.f;
    for (int j = s0; j < s1; j++) {
        const float* hr = h + (size_t)g_srcl[j] * DD;
        a0 += hr[t];
        a1 += hr[t + 128];
        if (v2) a2 += hr[t + 256];
    }
    g_z0[base + t] = a0;
    g_z0[base + t + 128] = a1;
    if (v2) g_z0[base + t + 256] = a2;
}

// ---------------- SGEMM 128x128x8, 256 threads, 8x8 per thread ----------------
// phase 0: C(g_z1) = g_z0 @ B + bias
// phase 1: C(g_z0) = BNReLU(g_z1; mu1,rs1,gam,bet) @ B + bias
// Epilogue accumulates per-column sum / sumsq of C into g_colsum/g_colsq.
__global__ void __launch_bounds__(256, 2) k_gemm(
    const float* __restrict__ B, const float* __restrict__ bias,
    const float* __restrict__ gam, const float* __restrict__ bet,
    int phase)
{
    __shared__ __align__(16) float smem[2048];
    float (*As)[128] = (float (*)[128])smem;          // [8][128]
    float (*Bs)[128] = (float (*)[128])(smem + 1024); // [8][128]

    const float* __restrict__ A = phase ? g_z1 : g_z0;
    float* __restrict__ Cmat    = phase ? g_z0 : g_z1;

    int tid = threadIdx.x;
    int tx = tid & 15, ty = tid >> 4;
    int m0 = blockIdx.y * 128, n0 = blockIdx.x * 128;

    int arow = tid >> 1;          // 0..127
    int acol = (tid & 1) * 4;     // 0 or 4
    int brow = tid >> 5;          // 0..7
    int bcol = (tid & 31) * 4;    // 0..124

    float acc[8][8];
    #pragma unroll
    for (int i = 0; i < 8; i++)
        #pragma unroll
        for (int j = 0; j < 8; j++) acc[i][j] = 0.f;

    for (int k0 = 0; k0 < DD; k0 += 8) {
        float4 av = make_float4(0.f, 0.f, 0.f, 0.f);
        int gm = m0 + arow, gk = k0 + acol;
        if (gm < NN && gk < DD) {
            av = *(const float4*)(A + (size_t)gm * DD + gk);
            if (phase) {
                av.x = fmaxf((av.x - g_mu1[gk+0]) * g_rs1[gk+0] * gam[gk+0] + bet[gk+0], 0.f);
                av.y = fmaxf((av.y - g_mu1[gk+1]) * g_rs1[gk+1] * gam[gk+1] + bet[gk+1], 0.f);
                av.z = fmaxf((av.z - g_mu1[gk+2]) * g_rs1[gk+2] * gam[gk+2] + bet[gk+2], 0.f);
                av.w = fmaxf((av.w - g_mu1[gk+3]) * g_rs1[gk+3] * gam[gk+3] + bet[gk+3], 0.f);
            }
        }
        As[acol + 0][arow] = av.x;
        As[acol + 1][arow] = av.y;
        As[acol + 2][arow] = av.z;
        As[acol + 3][arow] = av.w;

        float4 bv = make_float4(0.f, 0.f, 0.f, 0.f);
        int gkb = k0 + brow, gn = n0 + bcol;
        if (gkb < DD && gn < DD)
            bv = *(const float4*)(B + (size_t)gkb * DD + gn);
        *(float4*)&Bs[brow][bcol] = bv;

        __syncthreads();

        #pragma unroll
        for (int kk = 0; kk < 8; kk++) {
            float a[8], b[8];
            *(float4*)(a)     = *(const float4*)&As[kk][ty * 8];
            *(float4*)(a + 4) = *(const float4*)&As[kk][ty * 8 + 4];
            *(float4*)(b)     = *(const float4*)&Bs[kk][tx * 8];
            *(float4*)(b + 4) = *(const float4*)&Bs[kk][tx * 8 + 4];
            #pragma unroll
            for (int i = 0; i < 8; i++)
                #pragma unroll
                for (int j = 0; j < 8; j++)
                    acc[i][j] += a[i] * b[j];
        }
        __syncthreads();
    }

    int gn0 = n0 + tx * 8;
    float bj[8];
    #pragma unroll
    for (int j = 0; j < 8; j++)
        bj[j] = (gn0 + j < DD) ? bias[gn0 + j] : 0.f;

    float csum[8], csq[8];
    #pragma unroll
    for (int j = 0; j < 8; j++) { csum[j] = 0.f; csq[j] = 0.f; }

    #pragma unroll
    for (int i = 0; i < 8; i++) {
        int gm = m0 + ty * 8 + i;
        if (gm >= NN) continue;
        float o[8];
        #pragma unroll
        for (int j = 0; j < 8; j++) {
            o[j] = acc[i][j] + bj[j];
            csum[j] += o[j];
            csq[j]  += o[j] * o[j];
        }
        float* crow = Cmat + (size_t)gm * DD;
        if (gn0 < DD)     *(float4*)(crow + gn0)     = make_float4(o[0], o[1], o[2], o[3]);
        if (gn0 + 4 < DD) *(float4*)(crow + gn0 + 4) = make_float4(o[4], o[5], o[6], o[7]);
    }

    float* red = smem;
    __syncthreads();
    #pragma unroll
    for (int j = 0; j < 8; j++) red[ty * 128 + tx * 8 + j] = csum[j];
    __syncthreads();
    #pragma unroll
    for (int st = 8; st > 0; st >>= 1) {
        if (ty < st)
            #pragma unroll
            for (int j = 0; j < 8; j++)
                red[ty * 128 + tx * 8 + j] += red[(ty + st) * 128 + tx * 8 + j];
        __syncthreads();
    }
    if (ty == 0) {
        #pragma unroll
        for (int j = 0; j < 8; j++) {
            int gn = gn0 + j;
            if (gn < DD) atomicAdd(&g_colsum[gn], red[tx * 8 + j]);
        }
    }
    __syncthreads();
    #pragma unroll
    for (int j = 0; j < 8; j++) red[ty * 128 + tx * 8 + j] = csq[j];
    __syncthreads();
    #pragma unroll
    for (int st = 8; st > 0; st >>= 1) {
        if (ty < st)
            #pragma unroll
            for (int j = 0; j < 8; j++)
                red[ty * 128 + tx * 8 + j] += red[(ty + st) * 128 + tx * 8 + j];
        __syncthreads();
    }
    if (ty == 0) {
        #pragma unroll
        for (int j = 0; j < 8; j++) {
            int gn = gn0 + j;
            if (gn < DD) atomicAdd(&g_colsq[gn], red[tx * 8 + j]);
        }
    }
}

__global__ void k_finalize(int phase) {
    int i = threadIdx.x;
    if (i >= DD) return;
    float m = g_colsum[i] * (1.f / NN);
    float v = g_colsq[i] * (1.f / NN) - m * m;
    float r = rsqrtf(v + BN_EPS);
    if (phase == 0) { g_mu1[i] = m; g_rs1[i] = r; }
    else            { g_mu2[i] = m; g_rs2[i] = r; }
    g_colsum[i] = 0.f;
    g_colsq[i] = 0.f;
}

__global__ void k_bnrelu(const float* __restrict__ gam, const float* __restrict__ bet) {
    size_t i = (size_t)blockIdx.x * blockDim.x + threadIdx.x;
    if (i < (size_t)NN * DD) {
        int c = (int)(i % DD);
        float v = (g_z0[i] - g_mu2[c]) * g_rs2[c] * gam[c] + bet[c];
        g_hbuf[i] = fmaxf(v, 0.f);
    }
}

__global__ void k_pool(const float* __restrict__ x, int useX, int depth) {
    const float* __restrict__ h = useX ? x : g_hbuf;
    int g = blockIdx.x;
    int f = blockIdx.y * 128 + threadIdx.x;
    if (f >= DD) return;
    int s0 = g_goff[g], s1 = g_goff[g + 1];
    s0 = max(0, min(NN, s0));
    s1 = max(s0, min(NN, s1));
    float acc = 0.f;
    for (int i = s0; i < s1; i++) acc += h[(size_t)i * DD + f];
    float inv = 1.f / fmaxf((float)(s1 - s0), 1.f);
    g_pooled[((size_t)depth * NGR + g) * DD + f] = acc * inv;
}

__global__ void k_readout(const float* __restrict__ fcW, const float* __restrict__ fcb,
                          float* __restrict__ out) {
    __shared__ float sp[DD];
    int g = blockIdx.x, c = threadIdx.x; // 128 threads
    float acc = 0.f;
    for (int d = 0; d <= LL; d++) {
        const float* pr = g_pooled + ((size_t)d * NGR + g) * DD;
        for (int f = c; f < DD; f += 128) sp[f] = pr[f];
        __syncthreads();
        const float* W = fcW + (size_t)d * DD * CC;
        float a = 0.f;
        #pragma unroll 4
        for (int k = 0; k < DD; k++) a += sp[k] * W[k * CC + c];
        acc += a + fcb[d * CC + c];
        __syncthreads();
    }
    out[g * CC + c] = acc;
}

// ---------------- launch ----------------
extern "C" void kernel_launch(void* const* d_in, const int* in_sizes, int n_in,
                              void* d_out, int out_size) {
    const float* x     = (const float*)d_in[0];
    const void*  ei    = d_in[1];
    const void*  batch = d_in[2];
    const float* W1  = (const float*)d_in[3];
    const float* b1  = (const float*)d_in[4];
    const float* g1  = (const float*)d_in[5];
    const float* be1 = (const float*)d_in[6];
    const float* W2  = (const float*)d_in[7];
    const float* b2  = (const float*)d_in[8];
    const float* bng = (const float*)d_in[9];
    const float* bnb = (const float*)d_in[10];
    const float* fcW = (const float*)d_in[11];
    const float* fcb = (const float*)d_in[12];
    float* out = (float*)d_out;

    k_detect<<<1, 1>>>(ei);
    k_zero<<<(NN + 255) / 256, 256>>>();
    k_count<<<(EE + 255) / 256, 256>>>(ei);
    k_scan<<<1, 1024>>>();
    k_fill<<<(EE + 255) / 256, 256>>>(ei);
    k_goff<<<1, 288>>>(batch);

    dim3 pg(NGR, 3);
    k_pool<<<pg, 128>>>(x, 1, 0); // depth 0 pools x

    dim3 gg((DD + 127) / 128, (NN + 127) / 128); // (3, 391)
    for (int i = 0; i < LL; i++) {
        k_agg<<<NN, 128>>>(x, i == 0 ? 1 : 0);
        k_gemm<<<gg, 256>>>(W1 + (size_t)i * DD * DD, b1 + i * DD,
                            nullptr, nullptr, 0);
        k_finalize<<<1, 320>>>(0);
        k_gemm<<<gg, 256>>>(W2 + (size_t)i * DD * DD, b2 + i * DD,
                            g1 + i * DD, be1 + i * DD, 1);
        k_finalize<<<1, 320>>>(1);
        k_bnrelu<<<(int)(((size_t)NN * DD + 255) / 256), 256>>>(bng + i * DD, bnb + i * DD);
        k_pool<<<pg, 128>>>(x, 0, i + 1);
    }

    k_readout<<<NGR, 128>>>(fcW, fcb, out);
}

// round 7
// speedup vs baseline: 1.2271x; 1.2271x over previous
#include <cuda_runtime.h>
#include <cuda_bf16.h>
#include <cstdint>

#define NN 50000
#define EE 400000
#define DD 300
#define LL 5
#define CC 128
#define NGR 256
#define BN_EPS 1e-5f

// GEMM tiling: CTA 128x160, 8 warps (2M x 4N), warp 64x40, BK=16, 19 chunks
#define BM 128
#define BN 160
#define NCH 19
#define MT ((NN + BM - 1) / BM)   // 391
#define LDA 24
#define LDB 168

// ---------------- static device scratch ----------------
__device__ int   g_is64;
__device__ int   g_cnt[NN];
__device__ int   g_off[NN + 1];
__device__ int   g_pos[NN];
__device__ int   g_srcl[EE];
__device__ int   g_goff[NGR + 1];
__device__ int   g_bsum[128];
__device__ int   g_bpre[128];
__device__ __align__(16) float g_z0[(size_t)NN * DD];
__device__ __align__(16) float g_z1[(size_t)NN * DD];
__device__ __align__(16) float g_hbuf[(size_t)NN * DD];
__device__ float g_colsum[DD];
__device__ float g_colsq[DD];
__device__ __align__(16) float g_sc1[DD], g_sh1[DD], g_sc2[DD], g_sh2[DD];
__device__ __align__(16) float g_pooled[(size_t)(LL + 1) * NGR * DD];

__device__ __forceinline__ uint32_t smem_u32(const void* p) {
    uint32_t a;
    asm("{ .reg .u64 t; cvta.to.shared.u64 t, %1; cvt.u32.u64 %0, t; }" : "=r"(a) : "l"(p));
    return a;
}
__device__ __forceinline__ void ldsm_x4(uint32_t* r, uint32_t addr) {
    asm volatile("ldmatrix.sync.aligned.m8n8.x4.shared.b16 {%0,%1,%2,%3}, [%4];"
                 : "=r"(r[0]), "=r"(r[1]), "=r"(r[2]), "=r"(r[3]) : "r"(addr));
}
__device__ __forceinline__ void ldsm_x2t(uint32_t* r, uint32_t addr) {
    asm volatile("ldmatrix.sync.aligned.m8n8.x2.trans.shared.b16 {%0,%1}, [%2];"
                 : "=r"(r[0]), "=r"(r[1]) : "r"(addr));
}
__device__ __forceinline__ void mma16816(float* d, const uint32_t* a, const uint32_t* b) {
    asm volatile("mma.sync.aligned.m16n8k16.row.col.f32.bf16.bf16.f32 "
                 "{%0,%1,%2,%3}, {%4,%5,%6,%7}, {%8,%9}, {%0,%1,%2,%3};"
                 : "+f"(d[0]), "+f"(d[1]), "+f"(d[2]), "+f"(d[3])
                 : "r"(a[0]), "r"(a[1]), "r"(a[2]), "r"(a[3]), "r"(b[0]), "r"(b[1]));
}

__device__ __forceinline__ int idx_at(const void* p, long long i) {
    if (g_is64) return (int)((const long long*)p)[i];
    return ((const int*)p)[i];
}

// ---------------- setup kernels ----------------
__global__ void k_detect(const void* ei) {
    const int* w = (const int*)ei;
    int all0 = 1;
    for (int i = 0; i < 128; i++)
        if (w[2 * i + 1] != 0) { all0 = 0; break; }
    g_is64 = all0;
}

__global__ void k_zero() {
    int i = blockIdx.x * blockDim.x + threadIdx.x;
    if (i < NN) g_cnt[i] = 0;
    if (i < DD) { g_colsum[i] = 0.f; g_colsq[i] = 0.f; }
}

__global__ void k_count(const void* __restrict__ ei) {
    int e = blockIdx.x * blockDim.x + threadIdx.x;
    if (e < EE) {
        int d = idx_at(ei, (long long)EE + e);
        d = max(0, min(NN - 1, d));
        atomicAdd(&g_cnt[d], 1);
    }
}

__global__ void k_scan1() {
    __shared__ int s[512];
    int b = blockIdx.x, t = threadIdx.x, i = b * 512 + t;
    int v = (i < NN) ? g_cnt[i] : 0;
    s[t] = v;
    __syncthreads();
    for (int d = 1; d < 512; d <<= 1) {
        int y = (t >= d) ? s[t - d] : 0;
        __syncthreads();
        s[t] += y;
        __syncthreads();
    }
    if (i < NN) g_cnt[i] = s[t] - v;
    if (t == 511) g_bsum[b] = s[511];
}
__global__ void k_scan2(int nb) {
    __shared__ int s[128];
    int t = threadIdx.x;
    int v = (t < nb) ? g_bsum[t] : 0;
    s[t] = v;
    __syncthreads();
    for (int d = 1; d < 128; d <<= 1) {
        int y = (t >= d) ? s[t - d] : 0;
        __syncthreads();
        s[t] += y;
        __syncthreads();
    }
    if (t < nb) g_bpre[t] = s[t] - v;
    if (t == nb - 1) g_off[NN] = s[t];
}
__global__ void k_scan3() {
    int i = blockIdx.x * blockDim.x + threadIdx.x;
    if (i < NN) {
        int e = g_bpre[i >> 9] + g_cnt[i];
        g_off[i] = e;
        g_pos[i] = e;
    }
}

__global__ void k_fill(const void* __restrict__ ei) {
    int e = blockIdx.x * blockDim.x + threadIdx.x;
    if (e < EE) {
        int d = idx_at(ei, (long long)EE + e);
        d = max(0, min(NN - 1, d));
        int srcv = idx_at(ei, e);
        srcv = max(0, min(NN - 1, srcv));
        int p = atomicAdd(&g_pos[d], 1);
        if (p >= 0 && p < EE) g_srcl[p] = srcv;
    }
}

__global__ void k_goff(const void* __restrict__ batch) {
    int g = blockIdx.x * blockDim.x + threadIdx.x;
    if (g > NGR) return;
    int lo = 0, hi = NN;
    while (lo < hi) {
        int mid = (lo + hi) >> 1;
        if (idx_at(batch, mid) < g) lo = mid + 1; else hi = mid;
    }
    g_goff[g] = lo;
}

// ---------------- aggregation ----------------
__global__ void k_agg(const float* __restrict__ x, int useX) {
    const float* __restrict__ h = useX ? x : g_hbuf;
    int i = blockIdx.x;
    int t = threadIdx.x;
    size_t base = (size_t)i * DD;
    int s0 = g_off[i], s1 = g_off[i + 1];
    s0 = max(0, min(EE, s0));
    s1 = max(s0, min(EE, s1));
    bool v2 = (t < DD - 256);
    float a0 = h[base + t];
    float a1 = h[base + t + 128];
    float a2 = v2 ? h[base + t + 256] : 0.f;
    for (int j = s0; j < s1; j++) {
        const float* hr = h + (size_t)g_srcl[j] * DD;
        a0 += hr[t];
        a1 += hr[t + 128];
        if (v2) a2 += hr[t + 256];
    }
    g_z0[base + t] = a0;
    g_z0[base + t + 128] = a1;
    if (v2) g_z0[base + t + 256] = a2;
}

// ---------------- split-bf16 mma.sync GEMM ----------------
// phase 0: C(g_z1) = g_z0 @ Bw + bias
// phase 1: C(g_z0) = max(g_z1*sc1+sh1,0) @ Bw + bias
// Accumulates per-column sum/sumsq of C into g_colsum/g_colsq.
__global__ void __launch_bounds__(256) k_gemm_mma(
    const float* __restrict__ Bw, const float* __restrict__ bias, int phase)
{
    __shared__ __align__(16) __nv_bfloat16 Ah[BM][LDA], Al[BM][LDA];
    __shared__ __align__(16) __nv_bfloat16 Bh[16][LDB], Bl[16][LDB];

    const float* __restrict__ A = phase ? g_z1 : g_z0;
    float* __restrict__ C       = phase ? g_z0 : g_z1;

    int tid = threadIdx.x, lane = tid & 31, wid = tid >> 5;
    int warp_m = wid & 1, warp_n = wid >> 1;        // 2 x 4
    int m0 = blockIdx.y * BM, n0 = blockIdx.x * BN;

    // per-thread load mapping
    int arow0 = tid >> 1;                 // seg = tid*2+s -> row = seg>>2... recompute below
    (void)arow0;
    int brow = tid >> 4;                  // 0..15
    int bcb  = (tid & 15) * 10;           // 0..150

    float4 apre[2];
    float2 bpre[5];

    // ---- load chunk (k0) into prefetch regs ----
    #define LOAD_CHUNK(K0)                                                        \
    {                                                                             \
        _Pragma("unroll")                                                         \
        for (int s = 0; s < 2; s++) {                                             \
            int seg = tid * 2 + s;                                                \
            int r = seg >> 2, c = (seg & 3) * 4;                                  \
            int gm = m0 + r, gk = (K0) + c;                                       \
            float4 v = make_float4(0.f, 0.f, 0.f, 0.f);                           \
            if (gm < NN && gk < DD) {                                             \
                v = *(const float4*)(A + (size_t)gm * DD + gk);                   \
                if (phase) {                                                      \
                    float4 sc = *(const float4*)(g_sc1 + gk);                     \
                    float4 sh = *(const float4*)(g_sh1 + gk);                     \
                    v.x = fmaxf(v.x * sc.x + sh.x, 0.f);                          \
                    v.y = fmaxf(v.y * sc.y + sh.y, 0.f);                          \
                    v.z = fmaxf(v.z * sc.z + sh.z, 0.f);                          \
                    v.w = fmaxf(v.w * sc.w + sh.w, 0.f);                          \
                }                                                                 \
            }                                                                     \
            apre[s] = v;                                                          \
        }                                                                         \
        int gkb = (K0) + brow;                                                    \
        _Pragma("unroll")                                                         \
        for (int j = 0; j < 5; j++) {                                             \
            int col = bcb + 2 * j, gn = n0 + col;                                 \
            float2 w = make_float2(0.f, 0.f);                                     \
            if (gkb < DD && gn < DD)                                              \
                w = *(const float2*)(Bw + (size_t)gkb * DD + gn);                 \
            bpre[j] = w;                                                          \
        }                                                                         \
    }

    LOAD_CHUNK(0);

    float acc[4][5][4];
    #pragma unroll
    for (int mi = 0; mi < 4; mi++)
        #pragma unroll
        for (int ni = 0; ni < 5; ni++)
            #pragma unroll
            for (int q = 0; q < 4; q++) acc[mi][ni][q] = 0.f;

    for (int ch = 0; ch < NCH; ch++) {
        // ---- convert+store prefetch regs to smem ----
        #pragma unroll
        for (int s = 0; s < 2; s++) {
            int seg = tid * 2 + s;
            int r = seg >> 2, c = (seg & 3) * 4;
            float4 v = apre[s];
            __nv_bfloat162 h01 = __floats2bfloat162_rn(v.x, v.y);
            __nv_bfloat162 h23 = __floats2bfloat162_rn(v.z, v.w);
            float lx = v.x - __bfloat162float(h01.x);
            float ly = v.y - __bfloat162float(h01.y);
            float lz = v.z - __bfloat162float(h23.x);
            float lw = v.w - __bfloat162float(h23.y);
            *(__nv_bfloat162*)&Ah[r][c]     = h01;
            *(__nv_bfloat162*)&Ah[r][c + 2] = h23;
            *(__nv_bfloat162*)&Al[r][c]     = __floats2bfloat162_rn(lx, ly);
            *(__nv_bfloat162*)&Al[r][c + 2] = __floats2bfloat162_rn(lz, lw);
        }
        #pragma unroll
        for (int j = 0; j < 5; j++) {
            int col = bcb + 2 * j;
            float2 w = bpre[j];
            __nv_bfloat162 h = __floats2bfloat162_rn(w.x, w.y);
            float lx = w.x - __bfloat162float(h.x);
            float ly = w.y - __bfloat162float(h.y);
            *(__nv_bfloat162*)&Bh[brow][col] = h;
            *(__nv_bfloat162*)&Bl[brow][col] = __floats2bfloat162_rn(lx, ly);
        }
        __syncthreads();

        // ---- prefetch next chunk (LDGs in flight during mma) ----
        if (ch + 1 < NCH) { LOAD_CHUNK((ch + 1) * 16); }

        // ---- mma: 3 products ----
        int lr = lane & 15, lkh = (lane >> 4) * 8;
        uint32_t ah[4][4], al2[4][4], bh[5][2], bl2[5][2];
        #pragma unroll
        for (int mi = 0; mi < 4; mi++) {
            int r = warp_m * 64 + mi * 16 + lr;
            ldsm_x4(ah[mi], smem_u32(&Ah[r][lkh]));
        }
        #pragma unroll
        for (int ni = 0; ni < 5; ni++) {
            int col = warp_n * 40 + ni * 8;
            ldsm_x2t(bh[ni], smem_u32(&Bh[lr][col]));
        }
        #pragma unroll
        for (int mi = 0; mi < 4; mi++)
            #pragma unroll
            for (int ni = 0; ni < 5; ni++)
                mma16816(acc[mi][ni], ah[mi], bh[ni]);

        #pragma unroll
        for (int ni = 0; ni < 5; ni++) {
            int col = warp_n * 40 + ni * 8;
            ldsm_x2t(bl2[ni], smem_u32(&Bl[lr][col]));
        }
        #pragma unroll
        for (int mi = 0; mi < 4; mi++)
            #pragma unroll
            for (int ni = 0; ni < 5; ni++)
                mma16816(acc[mi][ni], ah[mi], bl2[ni]);

        #pragma unroll
        for (int mi = 0; mi < 4; mi++) {
            int r = warp_m * 64 + mi * 16 + lr;
            ldsm_x4(al2[mi], smem_u32(&Al[r][lkh]));
        }
        #pragma unroll
        for (int mi = 0; mi < 4; mi++)
            #pragma unroll
            for (int ni = 0; ni < 5; ni++)
                mma16816(acc[mi][ni], al2[mi], bh[ni]);

        __syncthreads();
    }
    #undef LOAD_CHUNK

    // ---- epilogue: bias, store, column stats ----
    float se[5], so[5], qe[5], qo[5];
    #pragma unroll
    for (int ni = 0; ni < 5; ni++) { se[ni] = so[ni] = qe[ni] = qo[ni] = 0.f; }

    #pragma unroll
    for (int mi = 0; mi < 4; mi++) {
        int r0 = m0 + warp_m * 64 + mi * 16 + (lane >> 2);
        int r1 = r0 + 8;
        bool v0 = r0 < NN, v1 = r1 < NN;
        #pragma unroll
        for (int ni = 0; ni < 5; ni++) {
            int gn = n0 + warp_n * 40 + ni * 8 + (lane & 3) * 2;
            bool vc = gn < DD;   // DD even, gn even -> pair valid together
            float b0v = vc ? bias[gn] : 0.f;
            float b1v = vc ? bias[gn + 1] : 0.f;
            float o0 = acc[mi][ni][0] + b0v;
            float o1 = acc[mi][ni][1] + b1v;
            float o2 = acc[mi][ni][2] + b0v;
            float o3 = acc[mi][ni][3] + b1v;
            if (v0 && vc) *(float2*)(C + (size_t)r0 * DD + gn) = make_float2(o0, o1);
            if (v1 && vc) *(float2*)(C + (size_t)r1 * DD + gn) = make_float2(o2, o3);
            if (v0) { se[ni] += o0; so[ni] += o1; qe[ni] += o0 * o0; qo[ni] += o1 * o1; }
            if (v1) { se[ni] += o2; so[ni] += o3; qe[ni] += o2 * o2; qo[ni] += o3 * o3; }
        }
    }
    #pragma unroll
    for (int ni = 0; ni < 5; ni++) {
        #pragma unroll
        for (int d = 4; d < 32; d <<= 1) {
            se[ni] += __shfl_xor_sync(0xffffffffu, se[ni], d);
            so[ni] += __shfl_xor_sync(0xffffffffu, so[ni], d);
            qe[ni] += __shfl_xor_sync(0xffffffffu, qe[ni], d);
            qo[ni] += __shfl_xor_sync(0xffffffffu, qo[ni], d);
        }
    }
    if (lane < 4) {
        #pragma unroll
        for (int ni = 0; ni < 5; ni++) {
            int gn = n0 + warp_n * 40 + ni * 8 + lane * 2;
            if (gn < DD) {
                atomicAdd(&g_colsum[gn], se[ni]);
                atomicAdd(&g_colsum[gn + 1], so[ni]);
                atomicAdd(&g_colsq[gn], qe[ni]);
                atomicAdd(&g_colsq[gn + 1], qo[ni]);
            }
        }
    }
}

// phase 0 -> sc1/sh1 (for GEMM2 A-transform), phase 1 -> sc2/sh2 (for k_bnrelu)
__global__ void k_finalize(int phase, const float* __restrict__ gam,
                           const float* __restrict__ bet) {
    int i = threadIdx.x;
    if (i >= DD) return;
    float m = g_colsum[i] * (1.f / NN);
    float v = g_colsq[i] * (1.f / NN) - m * m;
    float r = rsqrtf(v + BN_EPS);
    float sc = r * gam[i];
    float sh = bet[i] - m * sc;
    if (phase == 0) { g_sc1[i] = sc; g_sh1[i] = sh; }
    else            { g_sc2[i] = sc; g_sh2[i] = sh; }
    g_colsum[i] = 0.f;
    g_colsq[i] = 0.f;
}

__global__ void k_bnrelu() {
    size_t i = (size_t)blockIdx.x * blockDim.x + threadIdx.x;
    if (i < (size_t)NN * DD) {
        int c = (int)(i % DD);
        g_hbuf[i] = fmaxf(g_z0[i] * g_sc2[c] + g_sh2[c], 0.f);
    }
}

__global__ void k_pool(const float* __restrict__ x, int useX, int depth) {
    const float* __restrict__ h = useX ? x : g_hbuf;
    int g = blockIdx.x;
    int f = blockIdx.y * 128 + threadIdx.x;
    if (f >= DD) return;
    int s0 = g_goff[g], s1 = g_goff[g + 1];
    s0 = max(0, min(NN, s0));
    s1 = max(s0, min(NN, s1));
    float acc = 0.f;
    for (int i = s0; i < s1; i++) acc += h[(size_t)i * DD + f];
    float inv = 1.f / fmaxf((float)(s1 - s0), 1.f);
    g_pooled[((size_t)depth * NGR + g) * DD + f] = acc * inv;
}

__global__ void k_readout(const float* __restrict__ fcW, const float* __restrict__ fcb,
                          float* __restrict__ out) {
    __shared__ float sp[DD];
    int g = blockIdx.x, c = threadIdx.x;
    float acc = 0.f;
    for (int d = 0; d <= LL; d++) {
        const float* pr = g_pooled + ((size_t)d * NGR + g) * DD;
        for (int f = c; f < DD; f += 128) sp[f] = pr[f];
        __syncthreads();
        const float* W = fcW + (size_t)d * DD * CC;
        float a = 0.f;
        #pragma unroll 4
        for (int k = 0; k < DD; k++) a += sp[k] * W[k * CC + c];
        acc += a + fcb[d * CC + c];
        __syncthreads();
    }
    out[g * CC + c] = acc;
}

// ---------------- launch ----------------
extern "C" void kernel_launch(void* const* d_in, const int* in_sizes, int n_in,
                              void* d_out, int out_size) {
    const float* x     = (const float*)d_in[0];
    const void*  ei    = d_in[1];
    const void*  batch = d_in[2];
    const float* W1  = (const float*)d_in[3];
    const float* b1  = (const float*)d_in[4];
    const float* g1  = (const float*)d_in[5];
    const float* be1 = (const float*)d_in[6];
    const float* W2  = (const float*)d_in[7];
    const float* b2  = (const float*)d_in[8];
    const float* bng = (const float*)d_in[9];
    const float* bnb = (const float*)d_in[10];
    const float* fcW = (const float*)d_in[11];
    const float* fcb = (const float*)d_in[12];
    float* out = (float*)d_out;

    k_detect<<<1, 1>>>(ei);
    k_zero<<<(NN + 255) / 256, 256>>>();
    k_count<<<(EE + 255) / 256, 256>>>(ei);
    int nb = (NN + 511) / 512;  // 98
    k_scan1<<<nb, 512>>>();
    k_scan2<<<1, 128>>>(nb);
    k_scan3<<<(NN + 255) / 256, 256>>>();
    k_fill<<<(EE + 255) / 256, 256>>>(ei);
    k_goff<<<1, 288>>>(batch);

    dim3 pg(NGR, 3);
    k_pool<<<pg, 128>>>(x, 1, 0);

    dim3 gg(2, MT);  // (2, 391)
    for (int i = 0; i < LL; i++) {
        k_agg<<<NN, 128>>>(x, i == 0 ? 1 : 0);
        k_gemm_mma<<<gg, 256>>>(W1 + (size_t)i * DD * DD, b1 + i * DD, 0);
        k_finalize<<<1, 320>>>(0, g1 + i * DD, be1 + i * DD);
        k_gemm_mma<<<gg, 256>>>(W2 + (size_t)i * DD * DD, b2 + i * DD, 1);
        k_finalize<<<1, 320>>>(1, bng + i * DD, bnb + i * DD);
        k_bnrelu<<<(int)(((size_t)NN * DD + 255) / 256), 256>>>();
        k_pool<<<pg, 128>>>(x, 0, i + 1);
    }

    k_readout<<<NGR, 128>>>(fcW, fcb, out);
}

// round 8
// speedup vs baseline: 1.9277x; 1.5710x over previous
#include <cuda_runtime.h>
#include <cuda_bf16.h>
#include <cstdint>

#define NN 50000
#define NNP 50048             // padded rows (128*391)
#define EE 400000
#define DD 300
#define KP 304                // padded K (19*16), col 300 = bias row
#define WNP 320               // padded weight cols
#define LL 5
#define CC 128
#define NGR 256
#define BN_EPS 1e-5f

#define BM 128
#define BN 160
#define NCH 19
#define MT ((NNP) / BM)       // 391
#define LDA 24
#define LDB 168

// ---------------- static device scratch ----------------
__device__ int   g_is64;
__device__ int   g_cnt[NN];
__device__ int   g_off[NN + 1];
__device__ int   g_pos[NN];
__device__ int   g_srcl[EE];
__device__ int   g_goff[NGR + 1];
__device__ int   g_bsum[128];
__device__ int   g_bpre[128];
__device__ __align__(16) float g_z0[(size_t)NN * DD];
__device__ __align__(16) float g_z1[(size_t)NN * DD];
__device__ __align__(16) float g_hbuf[(size_t)NN * DD];
__device__ __align__(16) __nv_bfloat16 g_ahi[(size_t)NNP * KP];
__device__ __align__(16) __nv_bfloat16 g_alo[(size_t)NNP * KP];
__device__ __align__(16) __nv_bfloat16 g_whi[(size_t)2 * LL * KP * WNP];
__device__ __align__(16) __nv_bfloat16 g_wlo[(size_t)2 * LL * KP * WNP];
__device__ float g_colsum[DD];
__device__ float g_colsq[DD];
__device__ __align__(16) float g_sc1[DD], g_sh1[DD], g_sc2[DD], g_sh2[DD];
__device__ __align__(16) float g_pooled[(size_t)(LL + 1) * NGR * DD];

// ---------------- PTX helpers ----------------
__device__ __forceinline__ uint32_t smem_u32(const void* p) {
    uint32_t a;
    asm("{ .reg .u64 t; cvta.to.shared.u64 t, %1; cvt.u32.u64 %0, t; }" : "=r"(a) : "l"(p));
    return a;
}
__device__ __forceinline__ void cp16(uint32_t d, const void* s) {
    asm volatile("cp.async.cg.shared.global [%0], [%1], 16;" :: "r"(d), "l"(s) : "memory");
}
__device__ __forceinline__ void cp_commit() {
    asm volatile("cp.async.commit_group;" ::: "memory");
}
__device__ __forceinline__ void cp_wait0() {
    asm volatile("cp.async.wait_group 0;" ::: "memory");
}
__device__ __forceinline__ void ldsm_x4(uint32_t* r, uint32_t addr) {
    asm volatile("ldmatrix.sync.aligned.m8n8.x4.shared.b16 {%0,%1,%2,%3}, [%4];"
                 : "=r"(r[0]), "=r"(r[1]), "=r"(r[2]), "=r"(r[3]) : "r"(addr));
}
__device__ __forceinline__ void ldsm_x2t(uint32_t* r, uint32_t addr) {
    asm volatile("ldmatrix.sync.aligned.m8n8.x2.trans.shared.b16 {%0,%1}, [%2];"
                 : "=r"(r[0]), "=r"(r[1]) : "r"(addr));
}
__device__ __forceinline__ void mma16816(float* d, const uint32_t* a, const uint32_t* b) {
    asm volatile("mma.sync.aligned.m16n8k16.row.col.f32.bf16.bf16.f32 "
                 "{%0,%1,%2,%3}, {%4,%5,%6,%7}, {%8,%9}, {%0,%1,%2,%3};"
                 : "+f"(d[0]), "+f"(d[1]), "+f"(d[2]), "+f"(d[3])
                 : "r"(a[0]), "r"(a[1]), "r"(a[2]), "r"(a[3]), "r"(b[0]), "r"(b[1]));
}
__device__ __forceinline__ int idx_at(const void* p, long long i) {
    if (g_is64) return (int)((const long long*)p)[i];
    return ((const int*)p)[i];
}
__device__ __forceinline__ void store_split(size_t row, int col, float vx, float vy) {
    __nv_bfloat162 h = __floats2bfloat162_rn(vx, vy);
    float lx = vx - __bfloat162float(h.x);
    float ly = vy - __bfloat162float(h.y);
    *(__nv_bfloat162*)(g_ahi + row * KP + col) = h;
    *(__nv_bfloat162*)(g_alo + row * KP + col) = __floats2bfloat162_rn(lx, ly);
}

// ---------------- setup kernels ----------------
__global__ void k_detect(const void* ei) {
    const int* w = (const int*)ei;
    int all0 = 1;
    for (int i = 0; i < 128; i++)
        if (w[2 * i + 1] != 0) { all0 = 0; break; }
    g_is64 = all0;
}

// split weights (+bias row 300) into padded bf16 hi/lo planes, once per call
__global__ void k_wprep(const float* __restrict__ W1, const float* __restrict__ b1,
                        const float* __restrict__ W2, const float* __restrict__ b2) {
    int lw = blockIdx.x / KP;       // 0..9
    int k  = blockIdx.x % KP;       // 0..303
    int n  = threadIdx.x;           // 0..319
    int layer = lw >> 1;
    const float* W = (lw & 1) ? W2 : W1;
    const float* b = (lw & 1) ? b2 : b1;
    float v = 0.f;
    if (n < DD) {
        if (k < DD)       v = W[(size_t)layer * DD * DD + (size_t)k * DD + n];
        else if (k == DD) v = b[layer * DD + n];
    }
    __nv_bfloat16 h = __float2bfloat16(v);
    float l = v - __bfloat162float(h);
    size_t off = (size_t)lw * KP * WNP + (size_t)k * WNP + n;
    g_whi[off] = h;
    g_wlo[off] = __float2bfloat16(l);
}

// pad cols 300..303 (col300 = 1.0 in hi) for all rows; zero tail rows
__global__ void k_pad() {
    int row = blockIdx.x * 256 + threadIdx.x;
    if (row >= NNP) return;
    uint32_t* ph = (uint32_t*)(g_ahi + (size_t)row * KP + 300);
    uint32_t* pl = (uint32_t*)(g_alo + (size_t)row * KP + 300);
    ph[0] = 0x00003F80u; ph[1] = 0u;
    pl[0] = 0u; pl[1] = 0u;
    if (row >= NN) {
        uint32_t* rh = (uint32_t*)(g_ahi + (size_t)row * KP);
        uint32_t* rl = (uint32_t*)(g_alo + (size_t)row * KP);
        for (int c = 0; c < 150; c++) { rh[c] = 0u; rl[c] = 0u; }
    }
}

__global__ void k_zero() {
    int i = blockIdx.x * blockDim.x + threadIdx.x;
    if (i < NN) g_cnt[i] = 0;
    if (i < DD) { g_colsum[i] = 0.f; g_colsq[i] = 0.f; }
}

__global__ void k_count(const void* __restrict__ ei) {
    int e = blockIdx.x * blockDim.x + threadIdx.x;
    if (e < EE) {
        int d = idx_at(ei, (long long)EE + e);
        d = max(0, min(NN - 1, d));
        atomicAdd(&g_cnt[d], 1);
    }
}

__global__ void k_scan1() {
    __shared__ int s[512];
    int b = blockIdx.x, t = threadIdx.x, i = b * 512 + t;
    int v = (i < NN) ? g_cnt[i] : 0;
    s[t] = v;
    __syncthreads();
    for (int d = 1; d < 512; d <<= 1) {
        int y = (t >= d) ? s[t - d] : 0;
        __syncthreads();
        s[t] += y;
        __syncthreads();
    }
    if (i < NN) g_cnt[i] = s[t] - v;
    if (t == 511) g_bsum[b] = s[511];
}
__global__ void k_scan2(int nb) {
    __shared__ int s[128];
    int t = threadIdx.x;
    int v = (t < nb) ? g_bsum[t] : 0;
    s[t] = v;
    __syncthreads();
    for (int d = 1; d < 128; d <<= 1) {
        int y = (t >= d) ? s[t - d] : 0;
        __syncthreads();
        s[t] += y;
        __syncthreads();
    }
    if (t < nb) g_bpre[t] = s[t] - v;
    if (t == nb - 1) g_off[NN] = s[t];
}
__global__ void k_scan3() {
    int i = blockIdx.x * blockDim.x + threadIdx.x;
    if (i < NN) {
        int e = g_bpre[i >> 9] + g_cnt[i];
        g_off[i] = e;
        g_pos[i] = e;
    }
}

__global__ void k_fill(const void* __restrict__ ei) {
    int e = blockIdx.x * blockDim.x + threadIdx.x;
    if (e < EE) {
        int d = idx_at(ei, (long long)EE + e);
        d = max(0, min(NN - 1, d));
        int srcv = idx_at(ei, e);
        srcv = max(0, min(NN - 1, srcv));
        int p = atomicAdd(&g_pos[d], 1);
        if (p >= 0 && p < EE) g_srcl[p] = srcv;
    }
}

__global__ void k_goff(const void* __restrict__ batch) {
    int g = blockIdx.x * blockDim.x + threadIdx.x;
    if (g > NGR) return;
    int lo = 0, hi = NN;
    while (lo < hi) {
        int mid = (lo + hi) >> 1;
        if (idx_at(batch, mid) < g) lo = mid + 1; else hi = mid;
    }
    g_goff[g] = lo;
}

// ---------------- aggregation -> split bf16 planes ----------------
__global__ void k_agg(const float* __restrict__ x, int useX) {
    const float* __restrict__ h = useX ? x : g_hbuf;
    int i = blockIdx.x;
    int t = threadIdx.x;               // 128 threads, each handles col pairs
    size_t base = (size_t)i * DD;
    int s0 = g_off[i], s1 = g_off[i + 1];
    s0 = max(0, min(EE, s0));
    s1 = max(s0, min(EE, s1));
    bool v1 = (t < 22);                // pairs 128..149 -> cols 256..299
    float2 a0 = *(const float2*)(h + base + 2 * t);
    float2 a1 = v1 ? *(const float2*)(h + base + 256 + 2 * t) : make_float2(0.f, 0.f);
    for (int j = s0; j < s1; j++) {
        const float* hr = h + (size_t)g_srcl[j] * DD;
        float2 b0 = *(const float2*)(hr + 2 * t);
        a0.x += b0.x; a0.y += b0.y;
        if (v1) {
            float2 b1 = *(const float2*)(hr + 256 + 2 * t);
            a1.x += b1.x; a1.y += b1.y;
        }
    }
    store_split(i, 2 * t, a0.x, a0.y);
    if (v1) store_split(i, 256 + 2 * t, a1.x, a1.y);
}

// ---------------- tensor GEMM: C = A(split) @ W(split), bias via K-row ----------------
// phase 0: C = g_z1, phase 1: C = g_z0. Stats into g_colsum/g_colsq.
__global__ void __launch_bounds__(256) k_gemm(int widx, int phase) {
    __shared__ __align__(16) __nv_bfloat16 Ah[2][BM][LDA], Al[2][BM][LDA];
    __shared__ __align__(16) __nv_bfloat16 Bh[2][16][LDB], Bl[2][16][LDB];

    float* __restrict__ C = phase ? g_z0 : g_z1;
    const __nv_bfloat16* __restrict__ Whi = g_whi + (size_t)widx * KP * WNP;
    const __nv_bfloat16* __restrict__ Wlo = g_wlo + (size_t)widx * KP * WNP;

    int tid = threadIdx.x, lane = tid & 31, wid = tid >> 5;
    int warp_m = wid & 1, warp_n = wid >> 1;          // 2 x 4 warps
    int m0 = blockIdx.y * BM, n0 = blockIdx.x * BN;

    int arow = tid >> 1, aseg = tid & 1;
    const __nv_bfloat16* asrc_hi = g_ahi + (size_t)(m0 + arow) * KP + aseg * 8;
    const __nv_bfloat16* asrc_lo = g_alo + (size_t)(m0 + arow) * KP + aseg * 8;

    #define ISSUE(CH, ST)                                                       \
    {                                                                           \
        int k0i = (CH) * 16;                                                    \
        cp16(smem_u32(&Ah[ST][arow][aseg * 8]), asrc_hi + k0i);                 \
        cp16(smem_u32(&Al[ST][arow][aseg * 8]), asrc_lo + k0i);                 \
        for (int u = tid; u < 320; u += 256) {                                  \
            int br = u / 20, bc = u % 20;                                       \
            size_t go = (size_t)(k0i + br) * WNP + n0 + bc * 8;                 \
            cp16(smem_u32(&Bh[ST][br][bc * 8]), Whi + go);                      \
            cp16(smem_u32(&Bl[ST][br][bc * 8]), Wlo + go);                      \
        }                                                                       \
        cp_commit();                                                            \
    }

    ISSUE(0, 0);

    float acc[4][5][4];
    #pragma unroll
    for (int mi = 0; mi < 4; mi++)
        #pragma unroll
        for (int ni = 0; ni < 5; ni++)
            #pragma unroll
            for (int q = 0; q < 4; q++) acc[mi][ni][q] = 0.f;

    int lr = lane & 15, lkh = (lane >> 4) * 8;

    for (int ch = 0; ch < NCH; ch++) {
        cp_wait0();
        __syncthreads();
        int st = ch & 1;
        if (ch + 1 < NCH) ISSUE(ch + 1, st ^ 1);

        uint32_t ah[4][4], al[4][4], bh[5][2], bl[5][2];
        #pragma unroll
        for (int mi = 0; mi < 4; mi++)
            ldsm_x4(ah[mi], smem_u32(&Ah[st][warp_m * 64 + mi * 16 + lr][lkh]));
        #pragma unroll
        for (int ni = 0; ni < 5; ni++)
            ldsm_x2t(bh[ni], smem_u32(&Bh[st][lr][warp_n * 40 + ni * 8]));
        #pragma unroll
        for (int mi = 0; mi < 4; mi++)
            #pragma unroll
            for (int ni = 0; ni < 5; ni++)
                mma16816(acc[mi][ni], ah[mi], bh[ni]);

        #pragma unroll
        for (int ni = 0; ni < 5; ni++)
            ldsm_x2t(bl[ni], smem_u32(&Bl[st][lr][warp_n * 40 + ni * 8]));
        #pragma unroll
        for (int mi = 0; mi < 4; mi++)
            #pragma unroll
            for (int ni = 0; ni < 5; ni++)
                mma16816(acc[mi][ni], ah[mi], bl[ni]);

        #pragma unroll
        for (int mi = 0; mi < 4; mi++)
            ldsm_x4(al[mi], smem_u32(&Al[st][warp_m * 64 + mi * 16 + lr][lkh]));
        #pragma unroll
        for (int mi = 0; mi < 4; mi++)
            #pragma unroll
            for (int ni = 0; ni < 5; ni++)
                mma16816(acc[mi][ni], al[mi], bh[ni]);
    }
    #undef ISSUE

    // epilogue: store + column stats (bias already in accumulators via K-row)
    float se[5], so[5], qe[5], qo[5];
    #pragma unroll
    for (int ni = 0; ni < 5; ni++) { se[ni] = so[ni] = qe[ni] = qo[ni] = 0.f; }

    #pragma unroll
    for (int mi = 0; mi < 4; mi++) {
        int r0 = m0 + warp_m * 64 + mi * 16 + (lane >> 2);
        int r1 = r0 + 8;
        bool v0 = r0 < NN, v1 = r1 < NN;
        #pragma unroll
        for (int ni = 0; ni < 5; ni++) {
            int gn = n0 + warp_n * 40 + ni * 8 + (lane & 3) * 2;
            bool vc = gn < DD;
            float o0 = acc[mi][ni][0], o1 = acc[mi][ni][1];
            float o2 = acc[mi][ni][2], o3 = acc[mi][ni][3];
            if (v0 && vc) *(float2*)(C + (size_t)r0 * DD + gn) = make_float2(o0, o1);
            if (v1 && vc) *(float2*)(C + (size_t)r1 * DD + gn) = make_float2(o2, o3);
            if (v0) { se[ni] += o0; so[ni] += o1; qe[ni] += o0 * o0; qo[ni] += o1 * o1; }
            if (v1) { se[ni] += o2; so[ni] += o3; qe[ni] += o2 * o2; qo[ni] += o3 * o3; }
        }
    }
    #pragma unroll
    for (int ni = 0; ni < 5; ni++) {
        #pragma unroll
        for (int d = 4; d < 32; d <<= 1) {
            se[ni] += __shfl_xor_sync(0xffffffffu, se[ni], d);
            so[ni] += __shfl_xor_sync(0xffffffffu, so[ni], d);
            qe[ni] += __shfl_xor_sync(0xffffffffu, qe[ni], d);
            qo[ni] += __shfl_xor_sync(0xffffffffu, qo[ni], d);
        }
    }
    if (lane < 4) {
        #pragma unroll
        for (int ni = 0; ni < 5; ni++) {
            int gn = n0 + warp_n * 40 + ni * 8 + lane * 2;
            if (gn < DD) {
                atomicAdd(&g_colsum[gn], se[ni]);
                atomicAdd(&g_colsum[gn + 1], so[ni]);
                atomicAdd(&g_colsq[gn], qe[ni]);
                atomicAdd(&g_colsq[gn + 1], qo[ni]);
            }
        }
    }
}

// phase 0 -> sc1/sh1 (GEMM2 input transform), phase 1 -> sc2/sh2 (k_bnrelu)
__global__ void k_finalize(int phase, const float* __restrict__ gam,
                           const float* __restrict__ bet) {
    int i = threadIdx.x;
    if (i >= DD) return;
    float m = g_colsum[i] * (1.f / NN);
    float v = g_colsq[i] * (1.f / NN) - m * m;
    float r = rsqrtf(v + BN_EPS);
    float sc = r * gam[i];
    float sh = bet[i] - m * sc;
    if (phase == 0) { g_sc1[i] = sc; g_sh1[i] = sh; }
    else            { g_sc2[i] = sc; g_sh2[i] = sh; }
    g_colsum[i] = 0.f;
    g_colsq[i] = 0.f;
}

// split(relu(z1*sc1+sh1)) -> A planes (for GEMM2)
__global__ void k_bnsplit() {
    int idx = blockIdx.x * 256 + threadIdx.x;     // pair index
    if (idx >= NN * 150) return;
    int row = idx / 150, col = (idx - row * 150) * 2;
    float2 v = *(const float2*)(g_z1 + (size_t)row * DD + col);
    float ax = fmaxf(v.x * g_sc1[col] + g_sh1[col], 0.f);
    float ay = fmaxf(v.y * g_sc1[col + 1] + g_sh1[col + 1], 0.f);
    store_split(row, col, ax, ay);
}

// relu(z0*sc2+sh2) -> hbuf (fp32, for next agg + pool)
__global__ void k_bnrelu() {
    size_t i = (size_t)blockIdx.x * blockDim.x + threadIdx.x;
    if (i < (size_t)NN * DD) {
        int c = (int)(i % DD);
        g_hbuf[i] = fmaxf(g_z0[i] * g_sc2[c] + g_sh2[c], 0.f);
    }
}

__global__ void k_pool(const float* __restrict__ x, int useX, int depth) {
    const float* __restrict__ h = useX ? x : g_hbuf;
    int g = blockIdx.x;
    int f = blockIdx.y * 128 + threadIdx.x;
    if (f >= DD) return;
    int s0 = g_goff[g], s1 = g_goff[g + 1];
    s0 = max(0, min(NN, s0));
    s1 = max(s0, min(NN, s1));
    float acc = 0.f;
    for (int i = s0; i < s1; i++) acc += h[(size_t)i * DD + f];
    float inv = 1.f / fmaxf((float)(s1 - s0), 1.f);
    g_pooled[((size_t)depth * NGR + g) * DD + f] = acc * inv;
}

__global__ void k_readout(const float* __restrict__ fcW, const float* __restrict__ fcb,
                          float* __restrict__ out) {
    __shared__ float sp[DD];
    int g = blockIdx.x, c = threadIdx.x;
    float acc = 0.f;
    for (int d = 0; d <= LL; d++) {
        const float* pr = g_pooled + ((size_t)d * NGR + g) * DD;
        for (int f = c; f < DD; f += 128) sp[f] = pr[f];
        __syncthreads();
        const float* W = fcW + (size_t)d * DD * CC;
        float a = 0.f;
        #pragma unroll 4
        for (int k = 0; k < DD; k++) a += sp[k] * W[k * CC + c];
        acc += a + fcb[d * CC + c];
        __syncthreads();
    }
    out[g * CC + c] = acc;
}

// ---------------- launch ----------------
extern "C" void kernel_launch(void* const* d_in, const int* in_sizes, int n_in,
                              void* d_out, int out_size) {
    const float* x     = (const float*)d_in[0];
    const void*  ei    = d_in[1];
    const void*  batch = d_in[2];
    const float* W1  = (const float*)d_in[3];
    const float* b1  = (const float*)d_in[4];
    const float* g1  = (const float*)d_in[5];
    const float* be1 = (const float*)d_in[6];
    const float* W2  = (const float*)d_in[7];
    const float* b2  = (const float*)d_in[8];
    const float* bng = (const float*)d_in[9];
    const float* bnb = (const float*)d_in[10];
    const float* fcW = (const float*)d_in[11];
    const float* fcb = (const float*)d_in[12];
    float* out = (float*)d_out;

    k_detect<<<1, 1>>>(ei);
    k_wprep<<<2 * LL * KP, WNP>>>(W1, b1, W2, b2);
    k_pad<<<(NNP + 255) / 256, 256>>>();
    k_zero<<<(NN + 255) / 256, 256>>>();
    k_count<<<(EE + 255) / 256, 256>>>(ei);
    int nb = (NN + 511) / 512;  // 98
    k_scan1<<<nb, 512>>>();
    k_scan2<<<1, 128>>>(nb);
    k_scan3<<<(NN + 255) / 256, 256>>>();
    k_fill<<<(EE + 255) / 256, 256>>>(ei);
    k_goff<<<1, 288>>>(batch);

    dim3 pg(NGR, 3);
    k_pool<<<pg, 128>>>(x, 1, 0);

    dim3 gg(2, MT);   // (2, 391)
    for (int i = 0; i < LL; i++) {
        k_agg<<<NN, 128>>>(x, i == 0 ? 1 : 0);
        k_gemm<<<gg, 256>>>(2 * i, 0);
        k_finalize<<<1, 320>>>(0, g1 + i * DD, be1 + i * DD);
        k_bnsplit<<<(NN * 150 + 255) / 256, 256>>>();
        k_gemm<<<gg, 256>>>(2 * i + 1, 1);
        k_finalize<<<1, 320>>>(1, bng + i * DD, bnb + i * DD);
        k_bnrelu<<<(int)(((size_t)NN * DD + 255) / 256), 256>>>();
        k_pool<<<pg, 128>>>(x, 0, i + 1);
    }

    k_readout<<<NGR, 128>>>(fcW, fcb, out);
}

// round 9
// speedup vs baseline: 2.1498x; 1.1152x over previous
#include <cuda_runtime.h>
#include <cuda_bf16.h>
#include <cstdint>

#define NN 50000
#define NNP 50048
#define EE 400000
#define DD 300
#define KP 304
#define WNP 320
#define LL 5
#define CC 128
#define NGR 256
#define BN_EPS 1e-5f

#define BM 128
#define BN 160
#define NCH 19
#define MT ((NNP) / BM)
#define LDA 24
#define LDB 168
#define STG 3
#define SMEMSZ (STG * (BM * LDA + BM * LDA + 16 * LDB + 16 * LDB) * 2)  // 69120

// ---------------- static device scratch ----------------
__device__ int   g_is64;
__device__ int   g_cnt[NN];
__device__ int   g_off[NN + 1];
__device__ int   g_pos[NN];
__device__ int   g_srcl[EE];
__device__ int   g_goff[NGR + 1];
__device__ int   g_bsum[128];
__device__ int   g_bpre[128];
__device__ __align__(16) float g_z0[(size_t)NN * DD];
__device__ __align__(16) float g_z1[(size_t)NN * DD];
__device__ __align__(16) __nv_bfloat16 g_ahi[(size_t)NNP * KP];
__device__ __align__(16) __nv_bfloat16 g_alo[(size_t)NNP * KP];
__device__ __align__(16) __nv_bfloat16 g_whi[(size_t)2 * LL * KP * WNP];
__device__ __align__(16) __nv_bfloat16 g_wlo[(size_t)2 * LL * KP * WNP];
__device__ float g_colsum[DD];
__device__ float g_colsq[DD];
__device__ __align__(16) float g_sc1[DD], g_sh1[DD], g_sc2[DD], g_sh2[DD];
__device__ __align__(16) float g_pooled[(size_t)(LL + 1) * NGR * DD];

// ---------------- PTX helpers ----------------
__device__ __forceinline__ uint32_t smem_u32(const void* p) {
    uint32_t a;
    asm("{ .reg .u64 t; cvta.to.shared.u64 t, %1; cvt.u32.u64 %0, t; }" : "=r"(a) : "l"(p));
    return a;
}
__device__ __forceinline__ void cp16(uint32_t d, const void* s) {
    asm volatile("cp.async.cg.shared.global [%0], [%1], 16;" :: "r"(d), "l"(s) : "memory");
}
__device__ __forceinline__ void cp_commit() {
    asm volatile("cp.async.commit_group;" ::: "memory");
}
__device__ __forceinline__ void cp_wait0() {
    asm volatile("cp.async.wait_group 0;" ::: "memory");
}
__device__ __forceinline__ void cp_wait1() {
    asm volatile("cp.async.wait_group 1;" ::: "memory");
}
__device__ __forceinline__ void ldsm_x4(uint32_t* r, uint32_t addr) {
    asm volatile("ldmatrix.sync.aligned.m8n8.x4.shared.b16 {%0,%1,%2,%3}, [%4];"
                 : "=r"(r[0]), "=r"(r[1]), "=r"(r[2]), "=r"(r[3]) : "r"(addr));
}
__device__ __forceinline__ void ldsm_x2t(uint32_t* r, uint32_t addr) {
    asm volatile("ldmatrix.sync.aligned.m8n8.x2.trans.shared.b16 {%0,%1}, [%2];"
                 : "=r"(r[0]), "=r"(r[1]) : "r"(addr));
}
__device__ __forceinline__ void mma16816(float* d, const uint32_t* a, const uint32_t* b) {
    asm volatile("mma.sync.aligned.m16n8k16.row.col.f32.bf16.bf16.f32 "
                 "{%0,%1,%2,%3}, {%4,%5,%6,%7}, {%8,%9}, {%0,%1,%2,%3};"
                 : "+f"(d[0]), "+f"(d[1]), "+f"(d[2]), "+f"(d[3])
                 : "r"(a[0]), "r"(a[1]), "r"(a[2]), "r"(a[3]), "r"(b[0]), "r"(b[1]));
}
__device__ __forceinline__ int idx_at(const void* p, long long i) {
    if (g_is64) return (int)((const long long*)p)[i];
    return ((const int*)p)[i];
}
__device__ __forceinline__ void store_split(size_t row, int col, float vx, float vy) {
    __nv_bfloat162 h = __floats2bfloat162_rn(vx, vy);
    float lx = vx - __bfloat162float(h.x);
    float ly = vy - __bfloat162float(h.y);
    *(__nv_bfloat162*)(g_ahi + row * KP + col) = h;
    *(__nv_bfloat162*)(g_alo + row * KP + col) = __floats2bfloat162_rn(lx, ly);
}

// ---------------- setup kernels ----------------
__global__ void k_detect(const void* ei) {
    const int* w = (const int*)ei;
    int all0 = 1;
    for (int i = 0; i < 128; i++)
        if (w[2 * i + 1] != 0) { all0 = 0; break; }
    g_is64 = all0;
}

__global__ void k_wprep(const float* __restrict__ W1, const float* __restrict__ b1,
                        const float* __restrict__ W2, const float* __restrict__ b2) {
    int lw = blockIdx.x / KP;
    int k  = blockIdx.x % KP;
    int n  = threadIdx.x;
    int layer = lw >> 1;
    const float* W = (lw & 1) ? W2 : W1;
    const float* b = (lw & 1) ? b2 : b1;
    float v = 0.f;
    if (n < DD) {
        if (k < DD)       v = W[(size_t)layer * DD * DD + (size_t)k * DD + n];
        else if (k == DD) v = b[layer * DD + n];
    }
    __nv_bfloat16 h = __float2bfloat16(v);
    float l = v - __bfloat162float(h);
    size_t off = (size_t)lw * KP * WNP + (size_t)k * WNP + n;
    g_whi[off] = h;
    g_wlo[off] = __float2bfloat16(l);
}

__global__ void k_pad() {
    int row = blockIdx.x * 256 + threadIdx.x;
    if (row >= NNP) return;
    uint32_t* ph = (uint32_t*)(g_ahi + (size_t)row * KP + 300);
    uint32_t* pl = (uint32_t*)(g_alo + (size_t)row * KP + 300);
    ph[0] = 0x00003F80u; ph[1] = 0u;
    pl[0] = 0u; pl[1] = 0u;
    if (row >= NN) {
        uint32_t* rh = (uint32_t*)(g_ahi + (size_t)row * KP);
        uint32_t* rl = (uint32_t*)(g_alo + (size_t)row * KP);
        for (int c = 0; c < 150; c++) { rh[c] = 0u; rl[c] = 0u; }
    }
}

__global__ void k_zero() {
    int i = blockIdx.x * blockDim.x + threadIdx.x;
    if (i < NN) g_cnt[i] = 0;
    if (i < DD) { g_colsum[i] = 0.f; g_colsq[i] = 0.f; }
}

__global__ void k_count(const void* __restrict__ ei) {
    int e = blockIdx.x * blockDim.x + threadIdx.x;
    if (e < EE) {
        int d = idx_at(ei, (long long)EE + e);
        d = max(0, min(NN - 1, d));
        atomicAdd(&g_cnt[d], 1);
    }
}

__global__ void k_scan1() {
    __shared__ int s[512];
    int b = blockIdx.x, t = threadIdx.x, i = b * 512 + t;
    int v = (i < NN) ? g_cnt[i] : 0;
    s[t] = v;
    __syncthreads();
    for (int d = 1; d < 512; d <<= 1) {
        int y = (t >= d) ? s[t - d] : 0;
        __syncthreads();
        s[t] += y;
        __syncthreads();
    }
    if (i < NN) g_cnt[i] = s[t] - v;
    if (t == 511) g_bsum[b] = s[511];
}
__global__ void k_scan2(int nb) {
    __shared__ int s[128];
    int t = threadIdx.x;
    int v = (t < nb) ? g_bsum[t] : 0;
    s[t] = v;
    __syncthreads();
    for (int d = 1; d < 128; d <<= 1) {
        int y = (t >= d) ? s[t - d] : 0;
        __syncthreads();
        s[t] += y;
        __syncthreads();
    }
    if (t < nb) g_bpre[t] = s[t] - v;
    if (t == nb - 1) g_off[NN] = s[t];
}
__global__ void k_scan3() {
    int i = blockIdx.x * blockDim.x + threadIdx.x;
    if (i < NN) {
        int e = g_bpre[i >> 9] + g_cnt[i];
        g_off[i] = e;
        g_pos[i] = e;
    }
}

__global__ void k_fill(const void* __restrict__ ei) {
    int e = blockIdx.x * blockDim.x + threadIdx.x;
    if (e < EE) {
        int d = idx_at(ei, (long long)EE + e);
        d = max(0, min(NN - 1, d));
        int srcv = idx_at(ei, e);
        srcv = max(0, min(NN - 1, srcv));
        int p = atomicAdd(&g_pos[d], 1);
        if (p >= 0 && p < EE) g_srcl[p] = srcv;
    }
}

__global__ void k_goff(const void* __restrict__ batch) {
    int g = blockIdx.x * blockDim.x + threadIdx.x;
    if (g > NGR) return;
    int lo = 0, hi = NN;
    while (lo < hi) {
        int mid = (lo + hi) >> 1;
        if (idx_at(batch, mid) < g) lo = mid + 1; else hi = mid;
    }
    g_goff[g] = lo;
}

// ---------------- aggregation with fused BN-ReLU read of z0 ----------------
// useX=1: h = x raw. useX=0: h = relu(z0*sc2+sh2) computed on the fly.
__global__ void k_agg(const float* __restrict__ x, int useX) {
    const float* __restrict__ h = useX ? x : g_z0;
    int i = blockIdx.x;
    int t = threadIdx.x;
    size_t base = (size_t)i * DD;
    int s0 = g_off[i], s1 = g_off[i + 1];
    s0 = max(0, min(EE, s0));
    s1 = max(s0, min(EE, s1));
    bool v1 = (t < 22);
    float2 sc0 = make_float2(1.f, 1.f), sh0 = make_float2(0.f, 0.f);
    float2 sc1 = sc0, sh1 = sh0;
    if (!useX) {
        sc0 = *(const float2*)(g_sc2 + 2 * t);
        sh0 = *(const float2*)(g_sh2 + 2 * t);
        if (v1) {
            sc1 = *(const float2*)(g_sc2 + 256 + 2 * t);
            sh1 = *(const float2*)(g_sh2 + 256 + 2 * t);
        }
    }
    float2 a0 = *(const float2*)(h + base + 2 * t);
    float2 a1 = v1 ? *(const float2*)(h + base + 256 + 2 * t) : make_float2(0.f, 0.f);
    if (!useX) {
        a0.x = fmaxf(a0.x * sc0.x + sh0.x, 0.f);
        a0.y = fmaxf(a0.y * sc0.y + sh0.y, 0.f);
        a1.x = fmaxf(a1.x * sc1.x + sh1.x, 0.f);
        a1.y = fmaxf(a1.y * sc1.y + sh1.y, 0.f);
    }
    for (int j = s0; j < s1; j++) {
        const float* hr = h + (size_t)g_srcl[j] * DD;
        float2 b0 = *(const float2*)(hr + 2 * t);
        float2 b1 = v1 ? *(const float2*)(hr + 256 + 2 * t) : make_float2(0.f, 0.f);
        if (!useX) {
            b0.x = fmaxf(b0.x * sc0.x + sh0.x, 0.f);
            b0.y = fmaxf(b0.y * sc0.y + sh0.y, 0.f);
            b1.x = fmaxf(b1.x * sc1.x + sh1.x, 0.f);
            b1.y = fmaxf(b1.y * sc1.y + sh1.y, 0.f);
        }
        a0.x += b0.x; a0.y += b0.y;
        if (v1) { a1.x += b1.x; a1.y += b1.y; }
    }
    store_split(i, 2 * t, a0.x, a0.y);
    if (v1) store_split(i, 256 + 2 * t, a1.x, a1.y);
}

// ---------------- tensor GEMM: 3-stage cp.async, per-mi fragments ----------------
__global__ void __launch_bounds__(256, 2) k_gemm(int widx, int phase) {
    extern __shared__ __align__(16) char smem[];
    __nv_bfloat16* AhS = (__nv_bfloat16*)smem;            // [STG][BM][LDA]
    __nv_bfloat16* AlS = AhS + STG * BM * LDA;
    __nv_bfloat16* BhS = AlS + STG * BM * LDA;            // [STG][16][LDB]
    __nv_bfloat16* BlS = BhS + STG * 16 * LDB;

    float* __restrict__ C = phase ? g_z0 : g_z1;
    const __nv_bfloat16* __restrict__ Whi = g_whi + (size_t)widx * KP * WNP;
    const __nv_bfloat16* __restrict__ Wlo = g_wlo + (size_t)widx * KP * WNP;

    int tid = threadIdx.x, lane = tid & 31, wid = tid >> 5;
    int warp_m = wid & 1, warp_n = wid >> 1;
    int m0 = blockIdx.y * BM, n0 = blockIdx.x * BN;

    int arow = tid >> 1, aseg = tid & 1;
    const __nv_bfloat16* asrc_hi = g_ahi + (size_t)(m0 + arow) * KP + aseg * 8;
    const __nv_bfloat16* asrc_lo = g_alo + (size_t)(m0 + arow) * KP + aseg * 8;

    #define ISSUE(CH, ST)                                                       \
    {                                                                           \
        int k0i = (CH) * 16;                                                    \
        cp16(smem_u32(AhS + ((ST) * BM + arow) * LDA + aseg * 8), asrc_hi + k0i); \
        cp16(smem_u32(AlS + ((ST) * BM + arow) * LDA + aseg * 8), asrc_lo + k0i); \
        for (int u = tid; u < 320; u += 256) {                                  \
            int br = u / 20, bc = u % 20;                                       \
            size_t go = (size_t)(k0i + br) * WNP + n0 + bc * 8;                 \
            cp16(smem_u32(BhS + ((ST) * 16 + br) * LDB + bc * 8), Whi + go);    \
            cp16(smem_u32(BlS + ((ST) * 16 + br) * LDB + bc * 8), Wlo + go);    \
        }                                                                       \
        cp_commit();                                                            \
    }

    ISSUE(0, 0);
    ISSUE(1, 1);

    float acc[4][5][4];
    #pragma unroll
    for (int mi = 0; mi < 4; mi++)
        #pragma unroll
        for (int ni = 0; ni < 5; ni++)
            #pragma unroll
            for (int q = 0; q < 4; q++) acc[mi][ni][q] = 0.f;

    int lr = lane & 15, lkh = (lane >> 4) * 8;

    for (int ch = 0; ch < NCH; ch++) {
        if (ch + 2 < NCH) cp_wait1(); else cp_wait0();
        __syncthreads();
        int st = ch % 3;
        if (ch + 2 < NCH) ISSUE(ch + 2, (ch + 2) % 3);

        uint32_t bh[5][2], bl[5][2];
        #pragma unroll
        for (int ni = 0; ni < 5; ni++)
            ldsm_x2t(bh[ni], smem_u32(BhS + (st * 16 + lr) * LDB + warp_n * 40 + ni * 8));
        #pragma unroll
        for (int ni = 0; ni < 5; ni++)
            ldsm_x2t(bl[ni], smem_u32(BlS + (st * 16 + lr) * LDB + warp_n * 40 + ni * 8));

        #pragma unroll
        for (int mi = 0; mi < 4; mi++) {
            uint32_t ah[4], al[4];
            ldsm_x4(ah, smem_u32(AhS + (st * BM + warp_m * 64 + mi * 16 + lr) * LDA + lkh));
            #pragma unroll
            for (int ni = 0; ni < 5; ni++)
                mma16816(acc[mi][ni], ah, bh[ni]);
            #pragma unroll
            for (int ni = 0; ni < 5; ni++)
                mma16816(acc[mi][ni], ah, bl[ni]);
            ldsm_x4(al, smem_u32(AlS + (st * BM + warp_m * 64 + mi * 16 + lr) * LDA + lkh));
            #pragma unroll
            for (int ni = 0; ni < 5; ni++)
                mma16816(acc[mi][ni], al, bh[ni]);
        }
    }
    #undef ISSUE

    // epilogue: store + column stats (bias folded via K-row)
    float se[5], so[5], qe[5], qo[5];
    #pragma unroll
    for (int ni = 0; ni < 5; ni++) { se[ni] = so[ni] = qe[ni] = qo[ni] = 0.f; }

    #pragma unroll
    for (int mi = 0; mi < 4; mi++) {
        int r0 = m0 + warp_m * 64 + mi * 16 + (lane >> 2);
        int r1 = r0 + 8;
        bool v0 = r0 < NN, v1 = r1 < NN;
        #pragma unroll
        for (int ni = 0; ni < 5; ni++) {
            int gn = n0 + warp_n * 40 + ni * 8 + (lane & 3) * 2;
            bool vc = gn < DD;
            float o0 = acc[mi][ni][0], o1 = acc[mi][ni][1];
            float o2 = acc[mi][ni][2], o3 = acc[mi][ni][3];
            if (v0 && vc) *(float2*)(C + (size_t)r0 * DD + gn) = make_float2(o0, o1);
            if (v1 && vc) *(float2*)(C + (size_t)r1 * DD + gn) = make_float2(o2, o3);
            if (v0) { se[ni] += o0; so[ni] += o1; qe[ni] += o0 * o0; qo[ni] += o1 * o1; }
            if (v1) { se[ni] += o2; so[ni] += o3; qe[ni] += o2 * o2; qo[ni] += o3 * o3; }
        }
    }
    #pragma unroll
    for (int ni = 0; ni < 5; ni++) {
        #pragma unroll
        for (int d = 4; d < 32; d <<= 1) {
            se[ni] += __shfl_xor_sync(0xffffffffu, se[ni], d);
            so[ni] += __shfl_xor_sync(0xffffffffu, so[ni], d);
            qe[ni] += __shfl_xor_sync(0xffffffffu, qe[ni], d);
            qo[ni] += __shfl_xor_sync(0xffffffffu, qo[ni], d);
        }
    }
    if (lane < 4) {
        #pragma unroll
        for (int ni = 0; ni < 5; ni++) {
            int gn = n0 + warp_n * 40 + ni * 8 + lane * 2;
            if (gn < DD) {
                atomicAdd(&g_colsum[gn], se[ni]);
                atomicAdd(&g_colsum[gn + 1], so[ni]);
                atomicAdd(&g_colsq[gn], qe[ni]);
                atomicAdd(&g_colsq[gn + 1], qo[ni]);
            }
        }
    }
}

__global__ void k_finalize(int phase, const float* __restrict__ gam,
                           const float* __restrict__ bet) {
    int i = threadIdx.x;
    if (i >= DD) return;
    float m = g_colsum[i] * (1.f / NN);
    float v = g_colsq[i] * (1.f / NN) - m * m;
    float r = rsqrtf(v + BN_EPS);
    float sc = r * gam[i];
    float sh = bet[i] - m * sc;
    if (phase == 0) { g_sc1[i] = sc; g_sh1[i] = sh; }
    else            { g_sc2[i] = sc; g_sh2[i] = sh; }
    g_colsum[i] = 0.f;
    g_colsq[i] = 0.f;
}

// split(relu(z1*sc1+sh1)) -> A planes (GEMM2 input)
__global__ void k_bnsplit() {
    int idx = blockIdx.x * 256 + threadIdx.x;
    if (idx >= NN * 150) return;
    int row = idx / 150, col = (idx - row * 150) * 2;
    float2 v = *(const float2*)(g_z1 + (size_t)row * DD + col);
    float ax = fmaxf(v.x * g_sc1[col] + g_sh1[col], 0.f);
    float ay = fmaxf(v.y * g_sc1[col + 1] + g_sh1[col + 1], 0.f);
    store_split(row, col, ax, ay);
}

// pool with fused BN-ReLU read (useX=1: raw x; else relu(z0*sc2+sh2))
__global__ void k_pool(const float* __restrict__ x, int useX, int depth) {
    const float* __restrict__ h = useX ? x : g_z0;
    int g = blockIdx.x;
    int f = blockIdx.y * 128 + threadIdx.x;
    if (f >= DD) return;
    int s0 = g_goff[g], s1 = g_goff[g + 1];
    s0 = max(0, min(NN, s0));
    s1 = max(s0, min(NN, s1));
    float sc = 1.f, sh = 0.f;
    if (!useX) { sc = g_sc2[f]; sh = g_sh2[f]; }
    float acc = 0.f;
    for (int i = s0; i < s1; i++) {
        float v = h[(size_t)i * DD + f];
        if (!useX) v = fmaxf(v * sc + sh, 0.f);
        acc += v;
    }
    float inv = 1.f / fmaxf((float)(s1 - s0), 1.f);
    g_pooled[((size_t)depth * NGR + g) * DD + f] = acc * inv;
}

__global__ void k_readout(const float* __restrict__ fcW, const float* __restrict__ fcb,
                          float* __restrict__ out) {
    __shared__ float sp[DD];
    int g = blockIdx.x, c = threadIdx.x;
    float acc = 0.f;
    for (int d = 0; d <= LL; d++) {
        const float* pr = g_pooled + ((size_t)d * NGR + g) * DD;
        for (int f = c; f < DD; f += 128) sp[f] = pr[f];
        __syncthreads();
        const float* W = fcW + (size_t)d * DD * CC;
        float a = 0.f;
        #pragma unroll 4
        for (int k = 0; k < DD; k++) a += sp[k] * W[k * CC + c];
        acc += a + fcb[d * CC + c];
        __syncthreads();
    }
    out[g * CC + c] = acc;
}

// ---------------- launch ----------------
extern "C" void kernel_launch(void* const* d_in, const int* in_sizes, int n_in,
                              void* d_out, int out_size) {
    const float* x     = (const float*)d_in[0];
    const void*  ei    = d_in[1];
    const void*  batch = d_in[2];
    const float* W1  = (const float*)d_in[3];
    const float* b1  = (const float*)d_in[4];
    const float* g1  = (const float*)d_in[5];
    const float* be1 = (const float*)d_in[6];
    const float* W2  = (const float*)d_in[7];
    const float* b2  = (const float*)d_in[8];
    const float* bng = (const float*)d_in[9];
    const float* bnb = (const float*)d_in[10];
    const float* fcW = (const float*)d_in[11];
    const float* fcb = (const float*)d_in[12];
    float* out = (float*)d_out;

    cudaFuncSetAttribute(k_gemm, cudaFuncAttributeMaxDynamicSharedMemorySize, SMEMSZ);

    k_detect<<<1, 1>>>(ei);
    k_wprep<<<2 * LL * KP, WNP>>>(W1, b1, W2, b2);
    k_pad<<<(NNP + 255) / 256, 256>>>();
    k_zero<<<(NN + 255) / 256, 256>>>();
    k_count<<<(EE + 255) / 256, 256>>>(ei);
    int nb = (NN + 511) / 512;
    k_scan1<<<nb, 512>>>();
    k_scan2<<<1, 128>>>(nb);
    k_scan3<<<(NN + 255) / 256, 256>>>();
    k_fill<<<(EE + 255) / 256, 256>>>(ei);
    k_goff<<<1, 288>>>(batch);

    dim3 pg(NGR, 3);
    k_pool<<<pg, 128>>>(x, 1, 0);

    dim3 gg(2, MT);
    for (int i = 0; i < LL; i++) {
        k_agg<<<NN, 128>>>(x, i == 0 ? 1 : 0);
        k_gemm<<<gg, 256, SMEMSZ>>>(2 * i, 0);
        k_finalize<<<1, 320>>>(0, g1 + i * DD, be1 + i * DD);
        k_bnsplit<<<(NN * 150 + 255) / 256, 256>>>();
        k_gemm<<<gg, 256, SMEMSZ>>>(2 * i + 1, 1);
        k_finalize<<<1, 320>>>(1, bng + i * DD, bnb + i * DD);
        k_pool<<<pg, 128>>>(x, 0, i + 1);
    }

    k_readout<<<NGR, 128>>>(fcW, fcb, out);
}

// round 10
// speedup vs baseline: 2.4335x; 1.1320x over previous
#include <cuda_runtime.h>
#include <cuda_fp16.h>
#include <cstdint>

#define NN 50000
#define NNP 50048
#define EE 400000
#define DD 300
#define KP 304
#define WNP 320
#define LL 5
#define CC 128
#define NGR 256
#define BN_EPS 1e-5f

#define BM 128
#define BN 160
#define NCH 19
#define MT ((NNP) / BM)
#define LDA 24
#define LDB 168
#define STG 3
#define SMEMSZ (STG * (2 * BM * LDA + 16 * LDB) * 2)   // 52992

// ---------------- static device scratch ----------------
__device__ int   g_is64;
__device__ int   g_cnt[NN];
__device__ int   g_off[NN + 1];
__device__ int   g_pos[NN];
__device__ int   g_srcl[EE];
__device__ int   g_goff[NGR + 1];
__device__ int   g_bsum[128];
__device__ int   g_bpre[128];
__device__ __align__(16) float g_z0[(size_t)NN * DD];
__device__ __align__(16) float g_z1[(size_t)NN * DD];
__device__ __align__(16) __half g_ahi[(size_t)NNP * KP];
__device__ __align__(16) __half g_alo[(size_t)NNP * KP];
__device__ __align__(16) __half g_w[(size_t)2 * LL * KP * WNP];
__device__ float g_colsum[DD];
__device__ float g_colsq[DD];
__device__ __align__(16) float g_sc1[DD], g_sh1[DD], g_sc2[DD], g_sh2[DD];
__device__ __align__(16) float g_pooled[(size_t)(LL + 1) * NGR * DD];

// ---------------- PTX helpers ----------------
__device__ __forceinline__ uint32_t smem_u32(const void* p) {
    uint32_t a;
    asm("{ .reg .u64 t; cvta.to.shared.u64 t, %1; cvt.u32.u64 %0, t; }" : "=r"(a) : "l"(p));
    return a;
}
__device__ __forceinline__ void cp16(uint32_t d, const void* s) {
    asm volatile("cp.async.cg.shared.global [%0], [%1], 16;" :: "r"(d), "l"(s) : "memory");
}
__device__ __forceinline__ void cp_commit() {
    asm volatile("cp.async.commit_group;" ::: "memory");
}
__device__ __forceinline__ void cp_wait0() {
    asm volatile("cp.async.wait_group 0;" ::: "memory");
}
__device__ __forceinline__ void cp_wait1() {
    asm volatile("cp.async.wait_group 1;" ::: "memory");
}
__device__ __forceinline__ void ldsm_x4(uint32_t* r, uint32_t addr) {
    asm volatile("ldmatrix.sync.aligned.m8n8.x4.shared.b16 {%0,%1,%2,%3}, [%4];"
                 : "=r"(r[0]), "=r"(r[1]), "=r"(r[2]), "=r"(r[3]) : "r"(addr));
}
__device__ __forceinline__ void ldsm_x2t(uint32_t* r, uint32_t addr) {
    asm volatile("ldmatrix.sync.aligned.m8n8.x2.trans.shared.b16 {%0,%1}, [%2];"
                 : "=r"(r[0]), "=r"(r[1]) : "r"(addr));
}
__device__ __forceinline__ void mma16816(float* d, const uint32_t* a, const uint32_t* b) {
    asm volatile("mma.sync.aligned.m16n8k16.row.col.f32.f16.f16.f32 "
                 "{%0,%1,%2,%3}, {%4,%5,%6,%7}, {%8,%9}, {%0,%1,%2,%3};"
                 : "+f"(d[0]), "+f"(d[1]), "+f"(d[2]), "+f"(d[3])
                 : "r"(a[0]), "r"(a[1]), "r"(a[2]), "r"(a[3]), "r"(b[0]), "r"(b[1]));
}
__device__ __forceinline__ int idx_at(const void* p, long long i) {
    if (g_is64) return (int)((const long long*)p)[i];
    return ((const int*)p)[i];
}
__device__ __forceinline__ void store_split(size_t row, int col, float vx, float vy) {
    __half hx = __float2half_rn(vx), hy = __float2half_rn(vy);
    float lx = vx - __half2float(hx);
    float ly = vy - __half2float(hy);
    __half2 h2; h2.x = hx; h2.y = hy;
    __half2 l2; l2.x = __float2half_rn(lx); l2.y = __float2half_rn(ly);
    *(__half2*)(g_ahi + row * KP + col) = h2;
    *(__half2*)(g_alo + row * KP + col) = l2;
}

// ---------------- setup kernels ----------------
__global__ void k_detect(const void* ei) {
    const int* w = (const int*)ei;
    int all0 = 1;
    for (int i = 0; i < 128; i++)
        if (w[2 * i + 1] != 0) { all0 = 0; break; }
    g_is64 = all0;
}

// weights + bias row 300 -> single fp16 plane
__global__ void k_wprep(const float* __restrict__ W1, const float* __restrict__ b1,
                        const float* __restrict__ W2, const float* __restrict__ b2) {
    int lw = blockIdx.x / KP;
    int k  = blockIdx.x % KP;
    int n  = threadIdx.x;
    int layer = lw >> 1;
    const float* W = (lw & 1) ? W2 : W1;
    const float* b = (lw & 1) ? b2 : b1;
    float v = 0.f;
    if (n < DD) {
        if (k < DD)       v = W[(size_t)layer * DD * DD + (size_t)k * DD + n];
        else if (k == DD) v = b[layer * DD + n];
    }
    g_w[(size_t)lw * KP * WNP + (size_t)k * WNP + n] = __float2half_rn(v);
}

__global__ void k_pad() {
    int row = blockIdx.x * 256 + threadIdx.x;
    if (row >= NNP) return;
    uint32_t* ph = (uint32_t*)(g_ahi + (size_t)row * KP + 300);
    uint32_t* pl = (uint32_t*)(g_alo + (size_t)row * KP + 300);
    ph[0] = 0x00003C00u; ph[1] = 0u;   // fp16 {1.0, 0}, {0,0}
    pl[0] = 0u; pl[1] = 0u;
    if (row >= NN) {
        uint32_t* rh = (uint32_t*)(g_ahi + (size_t)row * KP);
        uint32_t* rl = (uint32_t*)(g_alo + (size_t)row * KP);
        for (int c = 0; c < 150; c++) { rh[c] = 0u; rl[c] = 0u; }
    }
}

__global__ void k_zero() {
    int i = blockIdx.x * blockDim.x + threadIdx.x;
    if (i < NN) g_cnt[i] = 0;
    if (i < DD) { g_colsum[i] = 0.f; g_colsq[i] = 0.f; }
}

__global__ void k_count(const void* __restrict__ ei) {
    int e = blockIdx.x * blockDim.x + threadIdx.x;
    if (e < EE) {
        int d = idx_at(ei, (long long)EE + e);
        d = max(0, min(NN - 1, d));
        atomicAdd(&g_cnt[d], 1);
    }
}

__global__ void k_scan1() {
    __shared__ int s[512];
    int b = blockIdx.x, t = threadIdx.x, i = b * 512 + t;
    int v = (i < NN) ? g_cnt[i] : 0;
    s[t] = v;
    __syncthreads();
    for (int d = 1; d < 512; d <<= 1) {
        int y = (t >= d) ? s[t - d] : 0;
        __syncthreads();
        s[t] += y;
        __syncthreads();
    }
    if (i < NN) g_cnt[i] = s[t] - v;
    if (t == 511) g_bsum[b] = s[511];
}
__global__ void k_scan2(int nb) {
    __shared__ int s[128];
    int t = threadIdx.x;
    int v = (t < nb) ? g_bsum[t] : 0;
    s[t] = v;
    __syncthreads();
    for (int d = 1; d < 128; d <<= 1) {
        int y = (t >= d) ? s[t - d] : 0;
        __syncthreads();
        s[t] += y;
        __syncthreads();
    }
    if (t < nb) g_bpre[t] = s[t] - v;
    if (t == nb - 1) g_off[NN] = s[t];
}
__global__ void k_scan3() {
    int i = blockIdx.x * blockDim.x + threadIdx.x;
    if (i < NN) {
        int e = g_bpre[i >> 9] + g_cnt[i];
        g_off[i] = e;
        g_pos[i] = e;
    }
}

__global__ void k_fill(const void* __restrict__ ei) {
    int e = blockIdx.x * blockDim.x + threadIdx.x;
    if (e < EE) {
        int d = idx_at(ei, (long long)EE + e);
        d = max(0, min(NN - 1, d));
        int srcv = idx_at(ei, e);
        srcv = max(0, min(NN - 1, srcv));
        int p = atomicAdd(&g_pos[d], 1);
        if (p >= 0 && p < EE) g_srcl[p] = srcv;
    }
}

__global__ void k_goff(const void* __restrict__ batch) {
    int g = blockIdx.x * blockDim.x + threadIdx.x;
    if (g > NGR) return;
    int lo = 0, hi = NN;
    while (lo < hi) {
        int mid = (lo + hi) >> 1;
        if (idx_at(batch, mid) < g) lo = mid + 1; else hi = mid;
    }
    g_goff[g] = lo;
}

// ---------------- aggregation with fused BN-ReLU read of z0 ----------------
__global__ void k_agg(const float* __restrict__ x, int useX) {
    const float* __restrict__ h = useX ? x : g_z0;
    int i = blockIdx.x;
    int t = threadIdx.x;
    size_t base = (size_t)i * DD;
    int s0 = g_off[i], s1 = g_off[i + 1];
    s0 = max(0, min(EE, s0));
    s1 = max(s0, min(EE, s1));
    bool v1 = (t < 22);
    float2 sc0 = make_float2(1.f, 1.f), sh0 = make_float2(0.f, 0.f);
    float2 sc1 = sc0, sh1 = sh0;
    if (!useX) {
        sc0 = *(const float2*)(g_sc2 + 2 * t);
        sh0 = *(const float2*)(g_sh2 + 2 * t);
        if (v1) {
            sc1 = *(const float2*)(g_sc2 + 256 + 2 * t);
            sh1 = *(const float2*)(g_sh2 + 256 + 2 * t);
        }
    }
    float2 a0 = *(const float2*)(h + base + 2 * t);
    float2 a1 = v1 ? *(const float2*)(h + base + 256 + 2 * t) : make_float2(0.f, 0.f);
    if (!useX) {
        a0.x = fmaxf(a0.x * sc0.x + sh0.x, 0.f);
        a0.y = fmaxf(a0.y * sc0.y + sh0.y, 0.f);
        a1.x = fmaxf(a1.x * sc1.x + sh1.x, 0.f);
        a1.y = fmaxf(a1.y * sc1.y + sh1.y, 0.f);
    }
    for (int j = s0; j < s1; j++) {
        const float* hr = h + (size_t)g_srcl[j] * DD;
        float2 b0 = *(const float2*)(hr + 2 * t);
        float2 b1 = v1 ? *(const float2*)(hr + 256 + 2 * t) : make_float2(0.f, 0.f);
        if (!useX) {
            b0.x = fmaxf(b0.x * sc0.x + sh0.x, 0.f);
            b0.y = fmaxf(b0.y * sc0.y + sh0.y, 0.f);
            b1.x = fmaxf(b1.x * sc1.x + sh1.x, 0.f);
            b1.y = fmaxf(b1.y * sc1.y + sh1.y, 0.f);
        }
        a0.x += b0.x; a0.y += b0.y;
        if (v1) { a1.x += b1.x; a1.y += b1.y; }
    }
    store_split(i, 2 * t, a0.x, a0.y);
    if (v1) store_split(i, 256 + 2 * t, a1.x, a1.y);
}

// ---------------- fp16 2-product GEMM: C = (Ah+Al) @ W ----------------
__global__ void __launch_bounds__(256, 2) k_gemm(int widx, int phase) {
    extern __shared__ __align__(16) char smem[];
    __half* AhS = (__half*)smem;                  // [STG][BM][LDA]
    __half* AlS = AhS + STG * BM * LDA;
    __half* BS  = AlS + STG * BM * LDA;           // [STG][16][LDB]

    float* __restrict__ C = phase ? g_z0 : g_z1;
    const __half* __restrict__ W = g_w + (size_t)widx * KP * WNP;

    int tid = threadIdx.x, lane = tid & 31, wid = tid >> 5;
    int warp_m = wid & 1, warp_n = wid >> 1;
    int m0 = blockIdx.y * BM, n0 = blockIdx.x * BN;

    int arow = tid >> 1, aseg = tid & 1;
    const __half* asrc_hi = g_ahi + (size_t)(m0 + arow) * KP + aseg * 8;
    const __half* asrc_lo = g_alo + (size_t)(m0 + arow) * KP + aseg * 8;

    #define ISSUE(CH, ST)                                                         \
    {                                                                             \
        int k0i = (CH) * 16;                                                      \
        cp16(smem_u32(AhS + ((ST) * BM + arow) * LDA + aseg * 8), asrc_hi + k0i); \
        cp16(smem_u32(AlS + ((ST) * BM + arow) * LDA + aseg * 8), asrc_lo + k0i); \
        for (int u = tid; u < 320; u += 256) {                                    \
            int br = u / 20, bc = u % 20;                                         \
            size_t go = (size_t)(k0i + br) * WNP + n0 + bc * 8;                   \
            cp16(smem_u32(BS + ((ST) * 16 + br) * LDB + bc * 8), W + go);         \
        }                                                                         \
        cp_commit();                                                              \
    }

    ISSUE(0, 0);
    ISSUE(1, 1);

    float acc[4][5][4];
    #pragma unroll
    for (int mi = 0; mi < 4; mi++)
        #pragma unroll
        for (int ni = 0; ni < 5; ni++)
            #pragma unroll
            for (int q = 0; q < 4; q++) acc[mi][ni][q] = 0.f;

    int lr = lane & 15, lkh = (lane >> 4) * 8;

    for (int ch = 0; ch < NCH; ch++) {
        if (ch + 2 < NCH) cp_wait1(); else cp_wait0();
        __syncthreads();
        int st = ch % 3;
        if (ch + 2 < NCH) ISSUE(ch + 2, (ch + 2) % 3);

        uint32_t bh[5][2];
        #pragma unroll
        for (int ni = 0; ni < 5; ni++)
            ldsm_x2t(bh[ni], smem_u32(BS + (st * 16 + lr) * LDB + warp_n * 40 + ni * 8));

        #pragma unroll
        for (int mi = 0; mi < 4; mi++) {
            uint32_t ah[4], al[4];
            ldsm_x4(ah, smem_u32(AhS + (st * BM + warp_m * 64 + mi * 16 + lr) * LDA + lkh));
            #pragma unroll
            for (int ni = 0; ni < 5; ni++)
                mma16816(acc[mi][ni], ah, bh[ni]);
            ldsm_x4(al, smem_u32(AlS + (st * BM + warp_m * 64 + mi * 16 + lr) * LDA + lkh));
            #pragma unroll
            for (int ni = 0; ni < 5; ni++)
                mma16816(acc[mi][ni], al, bh[ni]);
        }
    }
    #undef ISSUE

    // epilogue: store + column stats (bias folded via K-row)
    float se[5], so[5], qe[5], qo[5];
    #pragma unroll
    for (int ni = 0; ni < 5; ni++) { se[ni] = so[ni] = qe[ni] = qo[ni] = 0.f; }

    #pragma unroll
    for (int mi = 0; mi < 4; mi++) {
        int r0 = m0 + warp_m * 64 + mi * 16 + (lane >> 2);
        int r1 = r0 + 8;
        bool v0 = r0 < NN, v1 = r1 < NN;
        #pragma unroll
        for (int ni = 0; ni < 5; ni++) {
            int gn = n0 + warp_n * 40 + ni * 8 + (lane & 3) * 2;
            bool vc = gn < DD;
            float o0 = acc[mi][ni][0], o1 = acc[mi][ni][1];
            float o2 = acc[mi][ni][2], o3 = acc[mi][ni][3];
            if (v0 && vc) *(float2*)(C + (size_t)r0 * DD + gn) = make_float2(o0, o1);
            if (v1 && vc) *(float2*)(C + (size_t)r1 * DD + gn) = make_float2(o2, o3);
            if (v0) { se[ni] += o0; so[ni] += o1; qe[ni] += o0 * o0; qo[ni] += o1 * o1; }
            if (v1) { se[ni] += o2; so[ni] += o3; qe[ni] += o2 * o2; qo[ni] += o3 * o3; }
        }
    }
    #pragma unroll
    for (int ni = 0; ni < 5; ni++) {
        #pragma unroll
        for (int d = 4; d < 32; d <<= 1) {
            se[ni] += __shfl_xor_sync(0xffffffffu, se[ni], d);
            so[ni] += __shfl_xor_sync(0xffffffffu, so[ni], d);
            qe[ni] += __shfl_xor_sync(0xffffffffu, qe[ni], d);
            qo[ni] += __shfl_xor_sync(0xffffffffu, qo[ni], d);
        }
    }
    if (lane < 4) {
        #pragma unroll
        for (int ni = 0; ni < 5; ni++) {
            int gn = n0 + warp_n * 40 + ni * 8 + lane * 2;
            if (gn < DD) {
                atomicAdd(&g_colsum[gn], se[ni]);
                atomicAdd(&g_colsum[gn + 1], so[ni]);
                atomicAdd(&g_colsq[gn], qe[ni]);
                atomicAdd(&g_colsq[gn + 1], qo[ni]);
            }
        }
    }
}

__global__ void k_finalize(int phase, const float* __restrict__ gam,
                           const float* __restrict__ bet) {
    int i = threadIdx.x;
    if (i >= DD) return;
    float m = g_colsum[i] * (1.f / NN);
    float v = g_colsq[i] * (1.f / NN) - m * m;
    float r = rsqrtf(v + BN_EPS);
    float sc = r * gam[i];
    float sh = bet[i] - m * sc;
    if (phase == 0) { g_sc1[i] = sc; g_sh1[i] = sh; }
    else            { g_sc2[i] = sc; g_sh2[i] = sh; }
    g_colsum[i] = 0.f;
    g_colsq[i] = 0.f;
}

// split(relu(z1*sc1+sh1)) -> A planes (GEMM2 input)
__global__ void k_bnsplit() {
    int idx = blockIdx.x * 256 + threadIdx.x;
    if (idx >= NN * 150) return;
    int row = idx / 150, col = (idx - row * 150) * 2;
    float2 v = *(const float2*)(g_z1 + (size_t)row * DD + col);
    float ax = fmaxf(v.x * g_sc1[col] + g_sh1[col], 0.f);
    float ay = fmaxf(v.y * g_sc1[col + 1] + g_sh1[col + 1], 0.f);
    store_split(row, col, ax, ay);
}

// pool with fused BN-ReLU read
__global__ void k_pool(const float* __restrict__ x, int useX, int depth) {
    const float* __restrict__ h = useX ? x : g_z0;
    int g = blockIdx.x;
    int f = blockIdx.y * 128 + threadIdx.x;
    if (f >= DD) return;
    int s0 = g_goff[g], s1 = g_goff[g + 1];
    s0 = max(0, min(NN, s0));
    s1 = max(s0, min(NN, s1));
    float sc = 1.f, sh = 0.f;
    if (!useX) { sc = g_sc2[f]; sh = g_sh2[f]; }
    float acc = 0.f;
    for (int i = s0; i < s1; i++) {
        float v = h[(size_t)i * DD + f];
        if (!useX) v = fmaxf(v * sc + sh, 0.f);
        acc += v;
    }
    float inv = 1.f / fmaxf((float)(s1 - s0), 1.f);
    g_pooled[((size_t)depth * NGR + g) * DD + f] = acc * inv;
}

__global__ void k_readout(const float* __restrict__ fcW, const float* __restrict__ fcb,
                          float* __restrict__ out) {
    __shared__ float sp[DD];
    int g = blockIdx.x, c = threadIdx.x;
    float acc = 0.f;
    for (int d = 0; d <= LL; d++) {
        const float* pr = g_pooled + ((size_t)d * NGR + g) * DD;
        for (int f = c; f < DD; f += 128) sp[f] = pr[f];
        __syncthreads();
        const float* W = fcW + (size_t)d * DD * CC;
        float a = 0.f;
        #pragma unroll 4
        for (int k = 0; k < DD; k++) a += sp[k] * W[k * CC + c];
        acc += a + fcb[d * CC + c];
        __syncthreads();
    }
    out[g * CC + c] = acc;
}

// ---------------- launch ----------------
extern "C" void kernel_launch(void* const* d_in, const int* in_sizes, int n_in,
                              void* d_out, int out_size) {
    const float* x     = (const float*)d_in[0];
    const void*  ei    = d_in[1];
    const void*  batch = d_in[2];
    const float* W1  = (const float*)d_in[3];
    const float* b1  = (const float*)d_in[4];
    const float* g1  = (const float*)d_in[5];
    const float* be1 = (const float*)d_in[6];
    const float* W2  = (const float*)d_in[7];
    const float* b2  = (const float*)d_in[8];
    const float* bng = (const float*)d_in[9];
    const float* bnb = (const float*)d_in[10];
    const float* fcW = (const float*)d_in[11];
    const float* fcb = (const float*)d_in[12];
    float* out = (float*)d_out;

    cudaFuncSetAttribute(k_gemm, cudaFuncAttributeMaxDynamicSharedMemorySize, SMEMSZ);

    k_detect<<<1, 1>>>(ei);
    k_wprep<<<2 * LL * KP, WNP>>>(W1, b1, W2, b2);
    k_pad<<<(NNP + 255) / 256, 256>>>();
    k_zero<<<(NN + 255) / 256, 256>>>();
    k_count<<<(EE + 255) / 256, 256>>>(ei);
    int nb = (NN + 511) / 512;
    k_scan1<<<nb, 512>>>();
    k_scan2<<<1, 128>>>(nb);
    k_scan3<<<(NN + 255) / 256, 256>>>();
    k_fill<<<(EE + 255) / 256, 256>>>(ei);
    k_goff<<<1, 288>>>(batch);

    dim3 pg(NGR, 3);
    k_pool<<<pg, 128>>>(x, 1, 0);

    dim3 gg(2, MT);
    for (int i = 0; i < LL; i++) {
        k_agg<<<NN, 128>>>(x, i == 0 ? 1 : 0);
        k_gemm<<<gg, 256, SMEMSZ>>>(2 * i, 0);
        k_finalize<<<1, 320>>>(0, g1 + i * DD, be1 + i * DD);
        k_bnsplit<<<(NN * 150 + 255) / 256, 256>>>();
        k_gemm<<<gg, 256, SMEMSZ>>>(2 * i + 1, 1);
        k_finalize<<<1, 320>>>(1, bng + i * DD, bnb + i * DD);
        k_pool<<<pg, 128>>>(x, 0, i + 1);
    }

    k_readout<<<NGR, 128>>>(fcW, fcb, out);
}

// round 11
// speedup vs baseline: 2.9787x; 1.2241x over previous
#include <cuda_runtime.h>
#include <cuda_fp16.h>
#include <cstdint>

#define NN 50000
#define NNP 50048
#define EE 400000
#define DD 300
#define KP 304
#define WNP 320
#define LL 5
#define CC 128
#define NGR 256
#define BN_EPS 1e-5f

#define BM 128
#define BN 160
#define NCH 19
#define MT ((NNP) / BM)
#define LDA 24
#define LDB 168
#define STG 3
#define SMEMSZ (STG * (BM * LDA + 16 * LDB) * 2)   // 34560

// ---------------- static device scratch ----------------
__device__ int   g_is64;
__device__ int   g_cnt[NN];
__device__ int   g_off[NN + 1];
__device__ int   g_pos[NN];
__device__ int   g_srcl[EE];
__device__ int   g_goff[NGR + 1];
__device__ int   g_bsum[128];
__device__ int   g_bpre[128];
__device__ __align__(16) float g_z0[(size_t)NN * DD];
__device__ __align__(16) float g_z1[(size_t)NN * DD];
__device__ __align__(16) __half g_a[(size_t)NNP * KP];
__device__ __align__(16) __half g_w[(size_t)2 * LL * KP * WNP];
__device__ float g_colsum[DD];
__device__ float g_colsq[DD];
__device__ __align__(16) float g_sc1[DD], g_sh1[DD], g_sc2[DD], g_sh2[DD];
__device__ __align__(16) float g_pooled[(size_t)(LL + 1) * NGR * DD];

// ---------------- PTX helpers ----------------
__device__ __forceinline__ uint32_t smem_u32(const void* p) {
    uint32_t a;
    asm("{ .reg .u64 t; cvta.to.shared.u64 t, %1; cvt.u32.u64 %0, t; }" : "=r"(a) : "l"(p));
    return a;
}
__device__ __forceinline__ void cp16(uint32_t d, const void* s) {
    asm volatile("cp.async.cg.shared.global [%0], [%1], 16;" :: "r"(d), "l"(s) : "memory");
}
__device__ __forceinline__ void cp_commit() {
    asm volatile("cp.async.commit_group;" ::: "memory");
}
__device__ __forceinline__ void cp_wait0() {
    asm volatile("cp.async.wait_group 0;" ::: "memory");
}
__device__ __forceinline__ void cp_wait1() {
    asm volatile("cp.async.wait_group 1;" ::: "memory");
}
__device__ __forceinline__ void ldsm_x4(uint32_t* r, uint32_t addr) {
    asm volatile("ldmatrix.sync.aligned.m8n8.x4.shared.b16 {%0,%1,%2,%3}, [%4];"
                 : "=r"(r[0]), "=r"(r[1]), "=r"(r[2]), "=r"(r[3]) : "r"(addr));
}
__device__ __forceinline__ void ldsm_x2t(uint32_t* r, uint32_t addr) {
    asm volatile("ldmatrix.sync.aligned.m8n8.x2.trans.shared.b16 {%0,%1}, [%2];"
                 : "=r"(r[0]), "=r"(r[1]) : "r"(addr));
}
__device__ __forceinline__ void mma16816(float* d, const uint32_t* a, const uint32_t* b) {
    asm volatile("mma.sync.aligned.m16n8k16.row.col.f32.f16.f16.f32 "
                 "{%0,%1,%2,%3}, {%4,%5,%6,%7}, {%8,%9}, {%0,%1,%2,%3};"
                 : "+f"(d[0]), "+f"(d[1]), "+f"(d[2]), "+f"(d[3])
                 : "r"(a[0]), "r"(a[1]), "r"(a[2]), "r"(a[3]), "r"(b[0]), "r"(b[1]));
}
__device__ __forceinline__ int idx_at(const void* p, long long i) {
    if (g_is64) return (int)((const long long*)p)[i];
    return ((const int*)p)[i];
}
__device__ __forceinline__ void store_a(size_t row, int col, float vx, float vy) {
    __half2 h2;
    h2.x = __float2half_rn(vx);
    h2.y = __float2half_rn(vy);
    *(__half2*)(g_a + row * KP + col) = h2;
}

// ---------------- setup kernels ----------------
__global__ void k_detect(const void* ei) {
    const int* w = (const int*)ei;
    int all0 = 1;
    for (int i = 0; i < 128; i++)
        if (w[2 * i + 1] != 0) { all0 = 0; break; }
    g_is64 = all0;
}

// weights + bias row 300 -> fp16 plane
__global__ void k_wprep(const float* __restrict__ W1, const float* __restrict__ b1,
                        const float* __restrict__ W2, const float* __restrict__ b2) {
    int lw = blockIdx.x / KP;
    int k  = blockIdx.x % KP;
    int n  = threadIdx.x;
    int layer = lw >> 1;
    const float* W = (lw & 1) ? W2 : W1;
    const float* b = (lw & 1) ? b2 : b1;
    float v = 0.f;
    if (n < DD) {
        if (k < DD)       v = W[(size_t)layer * DD * DD + (size_t)k * DD + n];
        else if (k == DD) v = b[layer * DD + n];
    }
    g_w[(size_t)lw * KP * WNP + (size_t)k * WNP + n] = __float2half_rn(v);
}

__global__ void k_pad() {
    int row = blockIdx.x * 256 + threadIdx.x;
    if (row >= NNP) return;
    uint32_t* ph = (uint32_t*)(g_a + (size_t)row * KP + 300);
    ph[0] = 0x00003C00u; ph[1] = 0u;   // fp16 {1.0, 0}, {0, 0}
    if (row >= NN) {
        uint32_t* rh = (uint32_t*)(g_a + (size_t)row * KP);
        for (int c = 0; c < 150; c++) rh[c] = 0u;
    }
}

__global__ void k_zero() {
    int i = blockIdx.x * blockDim.x + threadIdx.x;
    if (i < NN) g_cnt[i] = 0;
    if (i < DD) { g_colsum[i] = 0.f; g_colsq[i] = 0.f; }
}

__global__ void k_count(const void* __restrict__ ei) {
    int e = blockIdx.x * blockDim.x + threadIdx.x;
    if (e < EE) {
        int d = idx_at(ei, (long long)EE + e);
        d = max(0, min(NN - 1, d));
        atomicAdd(&g_cnt[d], 1);
    }
}

__global__ void k_scan1() {
    __shared__ int s[512];
    int b = blockIdx.x, t = threadIdx.x, i = b * 512 + t;
    int v = (i < NN) ? g_cnt[i] : 0;
    s[t] = v;
    __syncthreads();
    for (int d = 1; d < 512; d <<= 1) {
        int y = (t >= d) ? s[t - d] : 0;
        __syncthreads();
        s[t] += y;
        __syncthreads();
    }
    if (i < NN) g_cnt[i] = s[t] - v;
    if (t == 511) g_bsum[b] = s[511];
}
__global__ void k_scan2(int nb) {
    __shared__ int s[128];
    int t = threadIdx.x;
    int v = (t < nb) ? g_bsum[t] : 0;
    s[t] = v;
    __syncthreads();
    for (int d = 1; d < 128; d <<= 1) {
        int y = (t >= d) ? s[t - d] : 0;
        __syncthreads();
        s[t] += y;
        __syncthreads();
    }
    if (t < nb) g_bpre[t] = s[t] - v;
    if (t == nb - 1) g_off[NN] = s[t];
}
__global__ void k_scan3() {
    int i = blockIdx.x * blockDim.x + threadIdx.x;
    if (i < NN) {
        int e = g_bpre[i >> 9] + g_cnt[i];
        g_off[i] = e;
        g_pos[i] = e;
    }
}

__global__ void k_fill(const void* __restrict__ ei) {
    int e = blockIdx.x * blockDim.x + threadIdx.x;
    if (e < EE) {
        int d = idx_at(ei, (long long)EE + e);
        d = max(0, min(NN - 1, d));
        int srcv = idx_at(ei, e);
        srcv = max(0, min(NN - 1, srcv));
        int p = atomicAdd(&g_pos[d], 1);
        if (p >= 0 && p < EE) g_srcl[p] = srcv;
    }
}

__global__ void k_goff(const void* __restrict__ batch) {
    int g = blockIdx.x * blockDim.x + threadIdx.x;
    if (g > NGR) return;
    int lo = 0, hi = NN;
    while (lo < hi) {
        int mid = (lo + hi) >> 1;
        if (idx_at(batch, mid) < g) lo = mid + 1; else hi = mid;
    }
    g_goff[g] = lo;
}

// ---------------- aggregation with fused BN-ReLU read of z0 ----------------
__global__ void k_agg(const float* __restrict__ x, int useX) {
    const float* __restrict__ h = useX ? x : g_z0;
    int i = blockIdx.x;
    int t = threadIdx.x;
    size_t base = (size_t)i * DD;
    int s0 = g_off[i], s1 = g_off[i + 1];
    s0 = max(0, min(EE, s0));
    s1 = max(s0, min(EE, s1));
    bool v1 = (t < 22);
    float2 sc0 = make_float2(1.f, 1.f), sh0 = make_float2(0.f, 0.f);
    float2 sc1 = sc0, sh1 = sh0;
    if (!useX) {
        sc0 = *(const float2*)(g_sc2 + 2 * t);
        sh0 = *(const float2*)(g_sh2 + 2 * t);
        if (v1) {
            sc1 = *(const float2*)(g_sc2 + 256 + 2 * t);
            sh1 = *(const float2*)(g_sh2 + 256 + 2 * t);
        }
    }
    float2 a0 = *(const float2*)(h + base + 2 * t);
    float2 a1 = v1 ? *(const float2*)(h + base + 256 + 2 * t) : make_float2(0.f, 0.f);
    if (!useX) {
        a0.x = fmaxf(a0.x * sc0.x + sh0.x, 0.f);
        a0.y = fmaxf(a0.y * sc0.y + sh0.y, 0.f);
        a1.x = fmaxf(a1.x * sc1.x + sh1.x, 0.f);
        a1.y = fmaxf(a1.y * sc1.y + sh1.y, 0.f);
    }
    for (int j = s0; j < s1; j++) {
        const float* hr = h + (size_t)g_srcl[j] * DD;
        float2 b0 = *(const float2*)(hr + 2 * t);
        float2 b1 = v1 ? *(const float2*)(hr + 256 + 2 * t) : make_float2(0.f, 0.f);
        if (!useX) {
            b0.x = fmaxf(b0.x * sc0.x + sh0.x, 0.f);
            b0.y = fmaxf(b0.y * sc0.y + sh0.y, 0.f);
            b1.x = fmaxf(b1.x * sc1.x + sh1.x, 0.f);
            b1.y = fmaxf(b1.y * sc1.y + sh1.y, 0.f);
        }
        a0.x += b0.x; a0.y += b0.y;
        if (v1) { a1.x += b1.x; a1.y += b1.y; }
    }
    store_a(i, 2 * t, a0.x, a0.y);
    if (v1) store_a(i, 256 + 2 * t, a1.x, a1.y);
}

// ---------------- fp16 single-product GEMM: C = A @ W ----------------
__global__ void __launch_bounds__(256, 2) k_gemm(int widx, int phase) {
    extern __shared__ __align__(16) char smem[];
    __half* AS = (__half*)smem;                   // [STG][BM][LDA]
    __half* BS = AS + STG * BM * LDA;             // [STG][16][LDB]

    float* __restrict__ C = phase ? g_z0 : g_z1;
    const __half* __restrict__ W = g_w + (size_t)widx * KP * WNP;

    int tid = threadIdx.x, lane = tid & 31, wid = tid >> 5;
    int warp_m = wid & 1, warp_n = wid >> 1;
    int m0 = blockIdx.y * BM, n0 = blockIdx.x * BN;

    int arow = tid >> 1, aseg = tid & 1;
    const __half* asrc = g_a + (size_t)(m0 + arow) * KP + aseg * 8;

    #define ISSUE(CH, ST)                                                         \
    {                                                                             \
        int k0i = (CH) * 16;                                                      \
        cp16(smem_u32(AS + ((ST) * BM + arow) * LDA + aseg * 8), asrc + k0i);     \
        for (int u = tid; u < 320; u += 256) {                                    \
            int br = u / 20, bc = u % 20;                                         \
            size_t go = (size_t)(k0i + br) * WNP + n0 + bc * 8;                   \
            cp16(smem_u32(BS + ((ST) * 16 + br) * LDB + bc * 8), W + go);         \
        }                                                                         \
        cp_commit();                                                              \
    }

    ISSUE(0, 0);
    ISSUE(1, 1);

    float acc[4][5][4];
    #pragma unroll
    for (int mi = 0; mi < 4; mi++)
        #pragma unroll
        for (int ni = 0; ni < 5; ni++)
            #pragma unroll
            for (int q = 0; q < 4; q++) acc[mi][ni][q] = 0.f;

    int lr = lane & 15, lkh = (lane >> 4) * 8;

    for (int ch = 0; ch < NCH; ch++) {
        if (ch + 2 < NCH) cp_wait1(); else cp_wait0();
        __syncthreads();
        int st = ch % 3;
        if (ch + 2 < NCH) ISSUE(ch + 2, (ch + 2) % 3);

        uint32_t bh[5][2];
        #pragma unroll
        for (int ni = 0; ni < 5; ni++)
            ldsm_x2t(bh[ni], smem_u32(BS + (st * 16 + lr) * LDB + warp_n * 40 + ni * 8));

        #pragma unroll
        for (int mi = 0; mi < 4; mi++) {
            uint32_t ah[4];
            ldsm_x4(ah, smem_u32(AS + (st * BM + warp_m * 64 + mi * 16 + lr) * LDA + lkh));
            #pragma unroll
            for (int ni = 0; ni < 5; ni++)
                mma16816(acc[mi][ni], ah, bh[ni]);
        }
    }
    #undef ISSUE

    // epilogue: store + column stats (bias folded via K-row)
    float se[5], so[5], qe[5], qo[5];
    #pragma unroll
    for (int ni = 0; ni < 5; ni++) { se[ni] = so[ni] = qe[ni] = qo[ni] = 0.f; }

    #pragma unroll
    for (int mi = 0; mi < 4; mi++) {
        int r0 = m0 + warp_m * 64 + mi * 16 + (lane >> 2);
        int r1 = r0 + 8;
        bool v0 = r0 < NN, v1 = r1 < NN;
        #pragma unroll
        for (int ni = 0; ni < 5; ni++) {
            int gn = n0 + warp_n * 40 + ni * 8 + (lane & 3) * 2;
            bool vc = gn < DD;
            float o0 = acc[mi][ni][0], o1 = acc[mi][ni][1];
            float o2 = acc[mi][ni][2], o3 = acc[mi][ni][3];
            if (v0 && vc) *(float2*)(C + (size_t)r0 * DD + gn) = make_float2(o0, o1);
            if (v1 && vc) *(float2*)(C + (size_t)r1 * DD + gn) = make_float2(o2, o3);
            if (v0) { se[ni] += o0; so[ni] += o1; qe[ni] += o0 * o0; qo[ni] += o1 * o1; }
            if (v1) { se[ni] += o2; so[ni] += o3; qe[ni] += o2 * o2; qo[ni] += o3 * o3; }
        }
    }
    #pragma unroll
    for (int ni = 0; ni < 5; ni++) {
        #pragma unroll
        for (int d = 4; d < 32; d <<= 1) {
            se[ni] += __shfl_xor_sync(0xffffffffu, se[ni], d);
            so[ni] += __shfl_xor_sync(0xffffffffu, so[ni], d);
            qe[ni] += __shfl_xor_sync(0xffffffffu, qe[ni], d);
            qo[ni] += __shfl_xor_sync(0xffffffffu, qo[ni], d);
        }
    }
    if (lane < 4) {
        #pragma unroll
        for (int ni = 0; ni < 5; ni++) {
            int gn = n0 + warp_n * 40 + ni * 8 + lane * 2;
            if (gn < DD) {
                atomicAdd(&g_colsum[gn], se[ni]);
                atomicAdd(&g_colsum[gn + 1], so[ni]);
                atomicAdd(&g_colsq[gn], qe[ni]);
                atomicAdd(&g_colsq[gn + 1], qo[ni]);
            }
        }
    }
}

__global__ void k_finalize(int phase, const float* __restrict__ gam,
                           const float* __restrict__ bet) {
    int i = threadIdx.x;
    if (i >= DD) return;
    float m = g_colsum[i] * (1.f / NN);
    float v = g_colsq[i] * (1.f / NN) - m * m;
    float r = rsqrtf(v + BN_EPS);
    float sc = r * gam[i];
    float sh = bet[i] - m * sc;
    if (phase == 0) { g_sc1[i] = sc; g_sh1[i] = sh; }
    else            { g_sc2[i] = sc; g_sh2[i] = sh; }
    g_colsum[i] = 0.f;
    g_colsq[i] = 0.f;
}

// relu(z1*sc1+sh1) -> A plane (GEMM2 input)
__global__ void k_bnsplit() {
    int idx = blockIdx.x * 256 + threadIdx.x;
    if (idx >= NN * 150) return;
    int row = idx / 150, col = (idx - row * 150) * 2;
    float2 v = *(const float2*)(g_z1 + (size_t)row * DD + col);
    float ax = fmaxf(v.x * g_sc1[col] + g_sh1[col], 0.f);
    float ay = fmaxf(v.y * g_sc1[col + 1] + g_sh1[col + 1], 0.f);
    store_a(row, col, ax, ay);
}

// pool with fused BN-ReLU read
__global__ void k_pool(const float* __restrict__ x, int useX, int depth) {
    const float* __restrict__ h = useX ? x : g_z0;
    int g = blockIdx.x;
    int f = blockIdx.y * 128 + threadIdx.x;
    if (f >= DD) return;
    int s0 = g_goff[g], s1 = g_goff[g + 1];
    s0 = max(0, min(NN, s0));
    s1 = max(s0, min(NN, s1));
    float sc = 1.f, sh = 0.f;
    if (!useX) { sc = g_sc2[f]; sh = g_sh2[f]; }
    float acc = 0.f;
    for (int i = s0; i < s1; i++) {
        float v = h[(size_t)i * DD + f];
        if (!useX) v = fmaxf(v * sc + sh, 0.f);
        acc += v;
    }
    float inv = 1.f / fmaxf((float)(s1 - s0), 1.f);
    g_pooled[((size_t)depth * NGR + g) * DD + f] = acc * inv;
}

__global__ void k_readout(const float* __restrict__ fcW, const float* __restrict__ fcb,
                          float* __restrict__ out) {
    __shared__ float sp[DD];
    int g = blockIdx.x, c = threadIdx.x;
    float acc = 0.f;
    for (int d = 0; d <= LL; d++) {
        const float* pr = g_pooled + ((size_t)d * NGR + g) * DD;
        for (int f = c; f < DD; f += 128) sp[f] = pr[f];
        __syncthreads();
        const float* W = fcW + (size_t)d * DD * CC;
        float a = 0.f;
        #pragma unroll 4
        for (int k = 0; k < DD; k++) a += sp[k] * W[k * CC + c];
        acc += a + fcb[d * CC + c];
        __syncthreads();
    }
    out[g * CC + c] = acc;
}

// ---------------- launch ----------------
extern "C" void kernel_launch(void* const* d_in, const int* in_sizes, int n_in,
                              void* d_out, int out_size) {
    const float* x     = (const float*)d_in[0];
    const void*  ei    = d_in[1];
    const void*  batch = d_in[2];
    const float* W1  = (const float*)d_in[3];
    const float* b1  = (const float*)d_in[4];
    const float* g1  = (const float*)d_in[5];
    const float* be1 = (const float*)d_in[6];
    const float* W2  = (const float*)d_in[7];
    const float* b2  = (const float*)d_in[8];
    const float* bng = (const float*)d_in[9];
    const float* bnb = (const float*)d_in[10];
    const float* fcW = (const float*)d_in[11];
    const float* fcb = (const float*)d_in[12];
    float* out = (float*)d_out;

    cudaFuncSetAttribute(k_gemm, cudaFuncAttributeMaxDynamicSharedMemorySize, SMEMSZ);

    k_detect<<<1, 1>>>(ei);
    k_wprep<<<2 * LL * KP, WNP>>>(W1, b1, W2, b2);
    k_pad<<<(NNP + 255) / 256, 256>>>();
    k_zero<<<(NN + 255) / 256, 256>>>();
    k_count<<<(EE + 255) / 256, 256>>>(ei);
    int nb = (NN + 511) / 512;
    k_scan1<<<nb, 512>>>();
    k_scan2<<<1, 128>>>(nb);
    k_scan3<<<(NN + 255) / 256, 256>>>();
    k_fill<<<(EE + 255) / 256, 256>>>(ei);
    k_goff<<<1, 288>>>(batch);

    dim3 pg(NGR, 3);
    k_pool<<<pg, 128>>>(x, 1, 0);

    dim3 gg(2, MT);
    for (int i = 0; i < LL; i++) {
        k_agg<<<NN, 128>>>(x, i == 0 ? 1 : 0);
        k_gemm<<<gg, 256, SMEMSZ>>>(2 * i, 0);
        k_finalize<<<1, 320>>>(0, g1 + i * DD, be1 + i * DD);
        k_bnsplit<<<(NN * 150 + 255) / 256, 256>>>();
        k_gemm<<<gg, 256, SMEMSZ>>>(2 * i + 1, 1);
        k_finalize<<<1, 320>>>(1, bng + i * DD, bnb + i * DD);
        k_pool<<<pg, 128>>>(x, 0, i + 1);
    }

    k_readout<<<NGR, 128>>>(fcW, fcb, out);
}